// round 15
// baseline (speedup 1.0000x reference)
#include <cuda_runtime.h>
#include <math.h>
#include <stdint.h>

// ---------------------------------------------------------------------------
// B=4, T=2048, C=1024, H=16, HS=64. M = 8192.
// GEMMs + attention on mma.sync.m16n8k8 tf32, fragment-packed operands.
// R15: cp.async (LDGSTS, 8cyc/op issue floor) replaced by cp.async.bulk +
// mbarrier. GEMM: 2x16KB bulk per chunk from ONE thread. Attention: 128
// 256B row-bulks, one per thread. Single-barrier pipelines kept from R13.
// ---------------------------------------------------------------------------
#define MROWS 8192
#define CDIM  1024

__device__ float g_ln1 [8192u * 1024];   // packed A
__device__ float g_qkv [8192u * 3072];   // natural, tf32-rounded
__device__ float g_attn[8192u * 1024];   // packed A
__device__ float g_x1  [8192u * 1024];   // natural
__device__ float g_ln2 [8192u * 1024];   // packed A
__device__ float g_hbuf[8192u * 4096];   // packed A
__device__ float g_w1p [1024u * 3072];   // packed B
__device__ float g_w2p [1024u * 1024];
__device__ float g_w3p [1024u * 4096];
__device__ float g_w4p [4096u * 1024];

// ---------------- helpers ----------------
__device__ __forceinline__ float tf32r(float x) {
    uint32_t u;
    asm("cvt.rna.tf32.f32 %0, %1;" : "=r"(u) : "f"(x));
    return __uint_as_float(u);
}
__device__ __forceinline__ uint32_t smem_u32(const void* p) {
    uint32_t a;
    asm("{ .reg .u64 t; cvta.to.shared.u64 t, %1; cvt.u32.u64 %0, t; }"
        : "=r"(a) : "l"(p));
    return a;
}
#define CP_ASYNC16(dst, src) \
    asm volatile("cp.async.cg.shared.global [%0], [%1], 16;" :: "r"(dst), "l"(src))
#define CP_COMMIT() asm volatile("cp.async.commit_group;" ::: "memory")
#define CP_WAIT0()  asm volatile("cp.async.wait_group 0;"  ::: "memory")

__device__ __forceinline__ void bulk_g2s(uint32_t dst, const void* src,
                                         uint32_t bytes, uint32_t mbar) {
    asm volatile(
        "cp.async.bulk.shared::cluster.global.mbarrier::complete_tx::bytes [%0], [%1], %2, [%3];"
        :: "r"(dst), "l"(src), "r"(bytes), "r"(mbar) : "memory");
}
#define MBARRIER_INIT(addr, cnt) \
    asm volatile("mbarrier.init.shared.b64 [%0], %1;" :: "r"(addr), "r"(cnt) : "memory")
#define MBARRIER_EXPECT_TX(addr, tx) \
    asm volatile("mbarrier.arrive.expect_tx.shared.b64 _, [%0], %1;" :: "r"(addr), "r"(tx) : "memory")
#define MBARRIER_WAIT_PARITY(addr, par) do { \
    uint32_t _m = (addr); uint32_t _p = (par); uint32_t _d; \
    asm volatile("{ .reg .pred p; mbarrier.try_wait.parity.acquire.cta.shared::cta.b64 p, [%1], %2; selp.b32 %0, 1, 0, p; }" \
        : "=r"(_d) : "r"(_m), "r"(_p) : "memory"); \
    if (!_d) { \
        asm volatile("{ .reg .pred P1; WL_%=: mbarrier.try_wait.parity.acquire.cta.shared::cta.b64 P1, [%0], %1, 0x989680; @P1 bra.uni WD_%=; bra.uni WL_%=; WD_%=: }" \
            :: "r"(_m), "r"(_p) : "memory"); \
    } } while (0)
#define FENCE_PROXY_ASYNC() asm volatile("fence.proxy.async.shared::cta;" ::: "memory")

__device__ __forceinline__ void mma_tf32(float c[4], uint32_t a0, uint32_t a1,
                                         uint32_t a2, uint32_t a3,
                                         uint32_t b0, uint32_t b1) {
    asm volatile(
        "mma.sync.aligned.m16n8k8.row.col.f32.tf32.tf32.f32 "
        "{%0,%1,%2,%3}, {%4,%5,%6,%7}, {%8,%9}, {%0,%1,%2,%3};"
        : "+f"(c[0]), "+f"(c[1]), "+f"(c[2]), "+f"(c[3])
        : "r"(a0), "r"(a1), "r"(a2), "r"(a3), "r"(b0), "r"(b1));
}

__device__ __forceinline__ float gelu_f(float x) {
    float x3 = x * x * x;
    return 0.5f * x * (1.0f + tanhf(0.7978845608028654f * (x + 0.044715f * x3)));
}

// Packed-A address (float index) for element (m,k) of an [M,K] A operand.
__device__ __forceinline__ size_t paddrA(int m, int k, int K) {
    const int mb = m >> 7, rm = m & 127;
    const int wm = rm >> 5, mt = (rm >> 4) & 1, lr = rm & 7, ah = (rm >> 3) & 1;
    const int kt = k >> 5, kk = (k >> 3) & 3, lc = k & 3, kh = (k >> 2) & 1;
    const int lane = lr * 4 + lc;
    const int reg  = ah + 2 * kh;
    return ((size_t)mb * (K >> 5) + kt) * 4096 +
           ((((kk * 4 + wm) * 2 + mt) * 32 + lane) * 4 + reg);
}
// Packed-B address (float index) for element (n,k) of W[K,N] viewed as [N,K].
__device__ __forceinline__ size_t paddrB(int n, int k, int K) {
    const int nb = n >> 7, rn = n & 127;
    const int wn = (rn >> 6) & 1, nt = (rn >> 3) & 7, n8 = rn & 7;
    const int kt = k >> 5, kk = (k >> 3) & 3, kh = (k >> 2) & 1;
    const int lane = n8 * 4 + (k & 3);
    return ((size_t)nb * (K >> 5) + kt) * 4096 +
           ((((kk * 2 + wn) * 8 + nt) * 32 + lane) * 2 + kh);
}

// ---------------------------------------------------------------------------
// LN body (shared by prep_kernel and ln_kernel)
// ---------------------------------------------------------------------------
__device__ __forceinline__ void ln_body(
    const float* __restrict__ x, const float* __restrict__ g,
    const float* __restrict__ b, float* __restrict__ o, int p, int tid)
{
    const int m0 = (p >> 3) * 16 + (p & 7);
    const int m1 = m0 + 8;
    const int k0 = ((tid >> 2) << 3) + (tid & 3);
    const int k1 = k0 + 512;

    const float* x0 = x + (size_t)m0 * CDIM;
    const float* x1 = x + (size_t)m1 * CDIM;
    const float a00 = x0[k0], a01 = x0[k0 + 4], a02 = x0[k1], a03 = x0[k1 + 4];
    const float a10 = x1[k0], a11 = x1[k0 + 4], a12 = x1[k1], a13 = x1[k1 + 4];

    float s0 = a00 + a01 + a02 + a03;
    float q0 = a00 * a00 + a01 * a01 + a02 * a02 + a03 * a03;
    float s1 = a10 + a11 + a12 + a13;
    float q1 = a10 * a10 + a11 * a11 + a12 * a12 + a13 * a13;

    #pragma unroll
    for (int off = 16; off > 0; off >>= 1) {
        s0 += __shfl_xor_sync(0xffffffffu, s0, off);
        q0 += __shfl_xor_sync(0xffffffffu, q0, off);
        s1 += __shfl_xor_sync(0xffffffffu, s1, off);
        q1 += __shfl_xor_sync(0xffffffffu, q1, off);
    }
    __shared__ float red[4][8];
    const int wid = tid >> 5;
    if ((tid & 31) == 0) {
        red[0][wid] = s0; red[1][wid] = q0; red[2][wid] = s1; red[3][wid] = q1;
    }
    __syncthreads();
    float ts0 = 0.f, tq0 = 0.f, ts1 = 0.f, tq1 = 0.f;
    #pragma unroll
    for (int w = 0; w < 8; w++) {
        ts0 += red[0][w]; tq0 += red[1][w]; ts1 += red[2][w]; tq1 += red[3][w];
    }

    const float mu0 = ts0 * (1.0f / CDIM);
    const float mu1 = ts1 * (1.0f / CDIM);
    const float r0 = rsqrtf(tq0 * (1.0f / CDIM) - mu0 * mu0 + 1e-5f);
    const float r1 = rsqrtf(tq1 * (1.0f / CDIM) - mu1 * mu1 + 1e-5f);

    #pragma unroll
    for (int gi = 0; gi < 2; gi++) {
        const int k = gi ? k1 : k0;
        const float ga = __ldg(&g[k]), gb = __ldg(&g[k + 4]);
        const float ba = __ldg(&b[k]), bb = __ldg(&b[k + 4]);
        const float xa0 = gi ? a02 : a00, xa1 = gi ? a03 : a01;
        const float xb0 = gi ? a12 : a10, xb1 = gi ? a13 : a11;
        *reinterpret_cast<float4*>(&o[paddrA(m0, k, CDIM)]) = make_float4(
            tf32r((xa0 - mu0) * r0 * ga + ba),
            tf32r((xb0 - mu1) * r1 * ga + ba),
            tf32r((xa1 - mu0) * r0 * gb + bb),
            tf32r((xb1 - mu1) * r1 * gb + bb));
    }
}

__device__ __forceinline__ void wprep_body(
    const float* __restrict__ W, float* __restrict__ O,
    int K, int N, int idx)
{
    const int n  = idx % N;
    const int kb = (idx / N) * 8;
    float v[8];
    #pragma unroll
    for (int i = 0; i < 8; i++)
        v[i] = tf32r(__ldg(&W[(size_t)(kb + i) * N + n]));
    float4* p = reinterpret_cast<float4*>(&O[paddrB(n, kb, K)]);
    p[0] = make_float4(v[0], v[4], v[1], v[5]);
    p[1] = make_float4(v[2], v[6], v[3], v[7]);
}

// ---------------------------------------------------------------------------
// prep_kernel: weights pack (blocks 0..6143) + LN1 (blocks 6144..10239)
// ---------------------------------------------------------------------------
__global__ __launch_bounds__(256) void prep_kernel(
    const float* __restrict__ w1, const float* __restrict__ w2,
    const float* __restrict__ w3, const float* __restrict__ w4,
    float* __restrict__ o1, float* __restrict__ o2,
    float* __restrict__ o3, float* __restrict__ o4,
    const float* __restrict__ x, const float* __restrict__ ln1_g,
    const float* __restrict__ ln1_b, float* __restrict__ ln1_o)
{
    const int bid = blockIdx.x;
    const int tid = threadIdx.x;
    if (bid < 1536)
        wprep_body(w1, o1, 1024, 3072, bid * 256 + tid);
    else if (bid < 2048)
        wprep_body(w2, o2, 1024, 1024, (bid - 1536) * 256 + tid);
    else if (bid < 4096)
        wprep_body(w3, o3, 1024, 4096, (bid - 2048) * 256 + tid);
    else if (bid < 6144)
        wprep_body(w4, o4, 4096, 1024, (bid - 4096) * 256 + tid);
    else
        ln_body(x, ln1_g, ln1_b, ln1_o, bid - 6144, tid);
}

__global__ __launch_bounds__(256) void ln_kernel(
    const float* __restrict__ x, const float* __restrict__ g,
    const float* __restrict__ b, float* __restrict__ o)
{
    ln_body(x, g, b, o, blockIdx.x, threadIdx.x);
}

// ---------------------------------------------------------------------------
// tf32 mma.sync GEMM, fragment-packed operands.
// 128 threads, 4 warps (2m x 2n), warp tile 64x64, GSTG=3, 2 CTAs/SM.
// Loads: cp.async.bulk (2 x 16KB per chunk) issued by thread 0 only;
// completion via per-stage mbarrier. Single barrier per chunk (R13 proof).
// Smem: [3 x 8B mbarriers][pad to 1024B][3 x 32KB stages].
// ---------------------------------------------------------------------------
#define GSTG 3
#define STG_FLOATS 8192
#define GEMM_SMEM (1024 + GSTG * STG_FLOATS * 4)

__global__ __launch_bounds__(128, 2) void mma_gemm(
    const float* __restrict__ Apk, const float* __restrict__ Bpk,
    const float* __restrict__ bias, const float* __restrict__ resid,
    float* __restrict__ C, int M, int N, int K, int act, int pack_out,
    int round_out)
{
    extern __shared__ float sm[];
    const uint32_t sb = smem_u32(sm);
    const uint32_t tiles_u = sb + 1024;
    float* tiles_f = sm + 256;

    const int tid  = threadIdx.x;
    const int wid  = tid >> 5;
    const int lane = tid & 31;
    const int wm = wid & 1;
    const int wn = wid >> 1;
    const int bm = blockIdx.y << 7;
    const int bn = blockIdx.x << 7;
    const int lr = lane >> 2;
    const int lc = lane & 3;

    const int nk = K >> 5;
    const char* abase = (const char*)Apk + (size_t)blockIdx.y * nk * 16384;
    const char* bbase = (const char*)Bpk + (size_t)blockIdx.x * nk * 16384;

    if (tid == 0) {
        #pragma unroll
        for (int s = 0; s < GSTG; s++) MBARRIER_INIT(sb + 8 * s, 1);
        FENCE_PROXY_ASYNC();
    }
    __syncthreads();

    float acc[4][8][4];
    #pragma unroll
    for (int at = 0; at < 4; at++)
        #pragma unroll
        for (int nt = 0; nt < 8; nt++)
            #pragma unroll
            for (int j = 0; j < 4; j++) acc[at][nt][j] = 0.f;

    #define ISSUEB(t) do { \
        if ((t) < nk && tid == 0) { \
            const uint32_t _m = sb + 8 * ((t) % GSTG); \
            const uint32_t _d = tiles_u + ((t) % GSTG) * 32768; \
            MBARRIER_EXPECT_TX(_m, 32768u); \
            bulk_g2s(_d,         abase + (size_t)(t) * 16384, 16384u, _m); \
            bulk_g2s(_d + 16384, bbase + (size_t)(t) * 16384, 16384u, _m); \
        } \
    } while (0)

    ISSUEB(0);
    ISSUEB(1);

    for (int t = 0; t < nk; t++) {
        MBARRIER_WAIT_PARITY(sb + 8 * (t % GSTG), (uint32_t)((t / GSTG) & 1));
        __syncthreads();   // all warps retired reads of stage t-1
        ISSUEB(t + 2);     // writes stage (t-1)%3 — safe post-sync

        const float* Ab = tiles_f + (t % GSTG) * STG_FLOATS;
        const float* Bb = Ab + 4096;
        #pragma unroll
        for (int kk = 0; kk < 4; kk++) {
            uint4 a[4];
            #pragma unroll
            for (int at = 0; at < 4; at++)
                a[at] = *reinterpret_cast<const uint4*>(
                    Ab + ((kk * 4 + wm * 2 + (at >> 1)) * 2 + (at & 1)) * 128 + lane * 4);
            const float* bq = Bb + (kk * 2 + wn) * 512 + lane * 2;
            #pragma unroll
            for (int nt = 0; nt < 8; nt++) {
                const uint2 bv = *reinterpret_cast<const uint2*>(bq + nt * 64);
                #pragma unroll
                for (int at = 0; at < 4; at++)
                    mma_tf32(acc[at][nt], a[at].x, a[at].y, a[at].z, a[at].w,
                             bv.x, bv.y);
            }
        }
    }

    #pragma unroll
    for (int at = 0; at < 4; at++) {
        const int r0 = bm + wm * 64 + (at >> 1) * 32 + (at & 1) * 16 + lr;
        const int r1 = r0 + 8;
        #pragma unroll
        for (int nt = 0; nt < 8; nt++) {
            const int col = bn + wn * 64 + nt * 8 + lc * 2;
            const float bb0 = __ldg(&bias[col]);
            const float bb1 = __ldg(&bias[col + 1]);
            float v0 = acc[at][nt][0] + bb0;
            float v1 = acc[at][nt][1] + bb1;
            float v2 = acc[at][nt][2] + bb0;
            float v3 = acc[at][nt][3] + bb1;
            if (act) {
                v0 = gelu_f(v0); v1 = gelu_f(v1);
                v2 = gelu_f(v2); v3 = gelu_f(v3);
            }
            if (pack_out) {
                const float u0 = __shfl_xor_sync(0xffffffffu, v0, 2);
                const float u1 = __shfl_xor_sync(0xffffffffu, v1, 2);
                const float u2 = __shfl_xor_sync(0xffffffffu, v2, 2);
                const float u3 = __shfl_xor_sync(0xffffffffu, v3, 2);
                if (lc < 2) {
                    *reinterpret_cast<float4*>(&C[paddrA(r0, col, N)]) =
                        make_float4(tf32r(v0), tf32r(v2), tf32r(u0), tf32r(u2));
                } else {
                    const int colo = col - 3;
                    *reinterpret_cast<float4*>(&C[paddrA(r0, colo, N)]) =
                        make_float4(tf32r(u1), tf32r(u3), tf32r(v1), tf32r(v3));
                }
            } else {
                const size_t o0 = (size_t)r0 * N + col;
                const size_t o1 = (size_t)r1 * N + col;
                if (resid) {
                    const float2 q0 = *reinterpret_cast<const float2*>(&resid[o0]);
                    const float2 q1 = *reinterpret_cast<const float2*>(&resid[o1]);
                    v0 += q0.x; v1 += q0.y; v2 += q1.x; v3 += q1.y;
                }
                if (round_out) {
                    v0 = tf32r(v0); v1 = tf32r(v1); v2 = tf32r(v2); v3 = tf32r(v3);
                }
                *reinterpret_cast<float2*>(&C[o0]) = make_float2(v0, v1);
                *reinterpret_cast<float2*>(&C[o1]) = make_float2(v2, v3);
            }
        }
    }
}

// ---------------------------------------------------------------------------
// Flash attention on mma.sync tf32, causal. CTA q-tile 128 (4 warps x 32 q).
// R13 structure; K/V loads via cp.async.bulk (64 row-copies of 256B each,
// one per thread) completing on per-buffer mbarriers. Q stays cp.async.
// Single barrier per iteration. Heavy-CTA-first.
// mbarriers at float offset 26624: [k0,k1,v0,v1] (8B each).
// ---------------------------------------------------------------------------
#define AST_K 68
#define AST_V 72
#define ATT_QOFF 0
#define ATT_KOFF(b) (8704 + (b) * 4352)
#define ATT_VOFF(b) (17408 + (b) * 4608)
#define ATT_MBAR 26624
#define ATT_SMEM (26624 * 4 + 64)

__global__ __launch_bounds__(128, 2) void attn_mma(
    const float* __restrict__ qkv, float* __restrict__ out)
{
    extern __shared__ float sm[];
    const uint32_t sb = smem_u32(sm);
    const int tid = threadIdx.x;
    const int w = tid >> 5, lane = tid & 31;
    const int lr = lane >> 2, lc = lane & 3;
    const int qt = (int)gridDim.x - 1 - (int)blockIdx.x;   // heavy CTAs first
    const int bh = blockIdx.y;
    const int b = bh >> 4, h = bh & 15;
    const int q0 = qt * 128;
    const float* basep = qkv + (size_t)b * 2048 * 3072 + (size_t)h * 64;

    const uint32_t kmb0 = sb + ATT_MBAR * 4;
    const uint32_t vmb0 = sb + ATT_MBAR * 4 + 16;

    if (tid == 0) {
        MBARRIER_INIT(kmb0,     1);
        MBARRIER_INIT(kmb0 + 8, 1);
        MBARRIER_INIT(vmb0,     1);
        MBARRIER_INIT(vmb0 + 8, 1);
        FENCE_PROXY_ASYNC();
    }
    __syncthreads();

    // K/V bulk issue: thread tid<64 -> K row tid; tid>=64 -> V row tid-64.
    #define ISSUE_KVB(kt_, bb) do { \
        if (tid == 0)  MBARRIER_EXPECT_TX(kmb0 + 8 * (bb), 16384u); \
        if (tid == 64) MBARRIER_EXPECT_TX(vmb0 + 8 * (bb), 16384u); \
        if (tid < 64) { \
            bulk_g2s(sb + (uint32_t)(ATT_KOFF(bb) + tid * AST_K) * 4, \
                     basep + (size_t)((kt_) * 64 + tid) * 3072 + 1024, \
                     256u, kmb0 + 8 * (bb)); \
        } else { \
            bulk_g2s(sb + (uint32_t)(ATT_VOFF(bb) + (tid - 64) * AST_V) * 4, \
                     basep + (size_t)((kt_) * 64 + tid - 64) * 3072 + 2048, \
                     256u, vmb0 + 8 * (bb)); \
        } \
    } while (0)

    // Q tile via cp.async (one-time)
    #pragma unroll
    for (int i = 0; i < 16; i++) {
        const int idx = tid + i * 128, row = idx >> 4, ch = idx & 15;
        CP_ASYNC16(sb + (uint32_t)(ATT_QOFF + row * AST_K + ch * 4) * 4,
                   basep + (size_t)(q0 + row) * 3072 + ch * 4);
    }
    CP_COMMIT();
    ISSUE_KVB(0, 0);

    CP_WAIT0();          // Q ready
    __syncthreads();

    float qa[2][8][4];
    {
        const float* Qs = sm + ATT_QOFF;
        #pragma unroll
        for (int mt2 = 0; mt2 < 2; mt2++) {
            const int r0 = w * 32 + mt2 * 16 + lr;
            #pragma unroll
            for (int kk = 0; kk < 8; kk++) {
                qa[mt2][kk][0] = 0.125f * Qs[r0 * AST_K + kk * 8 + lc];
                qa[mt2][kk][1] = 0.125f * Qs[(r0 + 8) * AST_K + kk * 8 + lc];
                qa[mt2][kk][2] = 0.125f * Qs[r0 * AST_K + kk * 8 + lc + 4];
                qa[mt2][kk][3] = 0.125f * Qs[(r0 + 8) * AST_K + kk * 8 + lc + 4];
            }
        }
    }
    __syncthreads();     // Q region becomes P region

    float* Pw = sm + ATT_QOFF + w * 2048;

    float m[2][2], l[2][2];
    #pragma unroll
    for (int i = 0; i < 2; i++)
        #pragma unroll
        for (int j2 = 0; j2 < 2; j2++) { m[i][j2] = -1e30f; l[i][j2] = 0.f; }

    float o[4][4][4];
    #pragma unroll
    for (int mt = 0; mt < 4; mt++)
        #pragma unroll
        for (int qn = 0; qn < 4; qn++)
            #pragma unroll
            for (int j = 0; j < 4; j++) o[mt][qn][j] = 0.f;

    const int ktmax = 2 * qt + 1;
    for (int kt = 0; kt <= ktmax; kt++) {
        const int buf = kt & 1;
        const uint32_t ph = (uint32_t)((kt >> 1) & 1);
        MBARRIER_WAIT_PARITY(kmb0 + 8 * buf, ph);
        MBARRIER_WAIT_PARITY(vmb0 + 8 * buf, ph);
        __syncthreads();   // retire reads of buf^1 (done in compute kt-1)
        if (kt < ktmax) ISSUE_KVB(kt + 1, buf ^ 1);   // safe post-sync

        if (64 * kt <= q0 + w * 32 + 31) {
            const float* Ks = sm + ATT_KOFF(buf);
            const float* Vs = sm + ATT_VOFF(buf);

            float s[2][8][4];
            #pragma unroll
            for (int mt2 = 0; mt2 < 2; mt2++)
                #pragma unroll
                for (int nt = 0; nt < 8; nt++)
                    #pragma unroll
                    for (int j = 0; j < 4; j++) s[mt2][nt][j] = 0.f;

            #pragma unroll
            for (int kk = 0; kk < 8; kk++) {
                #pragma unroll
                for (int nt = 0; nt < 8; nt++) {
                    const uint32_t b0 = __float_as_uint(Ks[(nt * 8 + lr) * AST_K + kk * 8 + lc]);
                    const uint32_t b1 = __float_as_uint(Ks[(nt * 8 + lr) * AST_K + kk * 8 + lc + 4]);
                    mma_tf32(s[0][nt],
                             __float_as_uint(qa[0][kk][0]), __float_as_uint(qa[0][kk][1]),
                             __float_as_uint(qa[0][kk][2]), __float_as_uint(qa[0][kk][3]),
                             b0, b1);
                    mma_tf32(s[1][nt],
                             __float_as_uint(qa[1][kk][0]), __float_as_uint(qa[1][kk][1]),
                             __float_as_uint(qa[1][kk][2]), __float_as_uint(qa[1][kk][3]),
                             b0, b1);
                }
            }

            #pragma unroll
            for (int mt2 = 0; mt2 < 2; mt2++) {
                const int rbase = q0 + w * 32 + mt2 * 16;
                if (64 * kt + 63 > rbase) {
                    #pragma unroll
                    for (int nt = 0; nt < 8; nt++) {
                        const int c = 64 * kt + nt * 8 + 2 * lc;
                        if (c     > rbase + lr)     s[mt2][nt][0] = -1e30f;
                        if (c + 1 > rbase + lr)     s[mt2][nt][1] = -1e30f;
                        if (c     > rbase + lr + 8) s[mt2][nt][2] = -1e30f;
                        if (c + 1 > rbase + lr + 8) s[mt2][nt][3] = -1e30f;
                    }
                }
            }

            float al[2][2];
            #pragma unroll
            for (int mt2 = 0; mt2 < 2; mt2++) {
                float mx0 = -1e30f, mx1 = -1e30f;
                #pragma unroll
                for (int nt = 0; nt < 8; nt++) {
                    mx0 = fmaxf(mx0, fmaxf(s[mt2][nt][0], s[mt2][nt][1]));
                    mx1 = fmaxf(mx1, fmaxf(s[mt2][nt][2], s[mt2][nt][3]));
                }
                mx0 = fmaxf(mx0, __shfl_xor_sync(0xffffffffu, mx0, 1));
                mx0 = fmaxf(mx0, __shfl_xor_sync(0xffffffffu, mx0, 2));
                mx1 = fmaxf(mx1, __shfl_xor_sync(0xffffffffu, mx1, 1));
                mx1 = fmaxf(mx1, __shfl_xor_sync(0xffffffffu, mx1, 2));

                const float mn0 = fmaxf(m[mt2][0], mx0);
                const float mn1 = fmaxf(m[mt2][1], mx1);
                al[mt2][0] = __expf(m[mt2][0] - mn0);
                al[mt2][1] = __expf(m[mt2][1] - mn1);
                m[mt2][0] = mn0; m[mt2][1] = mn1;

                float sum0 = 0.f, sum1 = 0.f;
                #pragma unroll
                for (int nt = 0; nt < 8; nt++) {
                    s[mt2][nt][0] = __expf(s[mt2][nt][0] - mn0); sum0 += s[mt2][nt][0];
                    s[mt2][nt][1] = __expf(s[mt2][nt][1] - mn0); sum0 += s[mt2][nt][1];
                    s[mt2][nt][2] = __expf(s[mt2][nt][2] - mn1); sum1 += s[mt2][nt][2];
                    s[mt2][nt][3] = __expf(s[mt2][nt][3] - mn1); sum1 += s[mt2][nt][3];
                }
                sum0 += __shfl_xor_sync(0xffffffffu, sum0, 1);
                sum0 += __shfl_xor_sync(0xffffffffu, sum0, 2);
                sum1 += __shfl_xor_sync(0xffffffffu, sum1, 1);
                sum1 += __shfl_xor_sync(0xffffffffu, sum1, 2);
                l[mt2][0] = l[mt2][0] * al[mt2][0] + sum0;
                l[mt2][1] = l[mt2][1] * al[mt2][1] + sum1;
            }

            #pragma unroll
            for (int qn = 0; qn < 4; qn++) {
                const float zA  = __shfl_sync(0xffffffffu, al[qn >> 1][qn & 1], 8 * lc);
                const float zAb = __shfl_sync(0xffffffffu, al[qn >> 1][qn & 1], 8 * lc + 4);
                #pragma unroll
                for (int mt = 0; mt < 4; mt++) {
                    o[mt][qn][0] *= zA;  o[mt][qn][1] *= zAb;
                    o[mt][qn][2] *= zA;  o[mt][qn][3] *= zAb;
                }
            }

            __syncwarp();
            {
                const int c0c = 2 * lc, c1c = 2 * lc + 1;
                const int ln0 = lr * 4 + (c0c & 3), rg0 = (c0c & 4) >> 2;
                const int ln1 = lr * 4 + (c1c & 3), rg1 = (c1c & 4) >> 2;
                #pragma unroll
                for (int mt2 = 0; mt2 < 2; mt2++) {
                    #pragma unroll
                    for (int nt = 0; nt < 8; nt++) {
                        const int q0n = mt2 * 2;
                        Pw[(nt * 4 + q0n + 0) * 64 + ln0 * 2 + rg0] = tf32r(s[mt2][nt][0]);
                        Pw[(nt * 4 + q0n + 0) * 64 + ln1 * 2 + rg1] = tf32r(s[mt2][nt][1]);
                        Pw[(nt * 4 + q0n + 1) * 64 + ln0 * 2 + rg0] = tf32r(s[mt2][nt][2]);
                        Pw[(nt * 4 + q0n + 1) * 64 + ln1 * 2 + rg1] = tf32r(s[mt2][nt][3]);
                    }
                }
            }
            __syncwarp();

            #pragma unroll
            for (int kk2 = 0; kk2 < 8; kk2++) {
                uint2 bp[4];
                #pragma unroll
                for (int qn = 0; qn < 4; qn++)
                    bp[qn] = *reinterpret_cast<const uint2*>(
                        Pw + (kk2 * 4 + qn) * 64 + lane * 2);
                #pragma unroll
                for (int mt = 0; mt < 4; mt++) {
                    const uint32_t a0 = __float_as_uint(Vs[(kk2 * 8 + lc) * AST_V + mt * 16 + lr]);
                    const uint32_t a1 = __float_as_uint(Vs[(kk2 * 8 + lc) * AST_V + mt * 16 + lr + 8]);
                    const uint32_t a2 = __float_as_uint(Vs[(kk2 * 8 + lc + 4) * AST_V + mt * 16 + lr]);
                    const uint32_t a3 = __float_as_uint(Vs[(kk2 * 8 + lc + 4) * AST_V + mt * 16 + lr + 8]);
                    #pragma unroll
                    for (int qn = 0; qn < 4; qn++)
                        mma_tf32(o[mt][qn], a0, a1, a2, a3, bp[qn].x, bp[qn].y);
                }
            }
        }
    }

    float zI[4], zIb[4];
    #pragma unroll
    for (int qn = 0; qn < 4; qn++) {
        const float inv = 1.0f / l[qn >> 1][qn & 1];
        zI[qn]  = __shfl_sync(0xffffffffu, inv, 8 * lc);
        zIb[qn] = __shfl_sync(0xffffffffu, inv, 8 * lc + 4);
    }

    #pragma unroll
    for (int mt = 0; mt < 4; mt++) {
        #pragma unroll
        for (int p = 0; p < 2; p++) {
            float f[2][4];
            #pragma unroll
            for (int h2 = 0; h2 < 2; h2++) {
                const int qn = 2 * p + h2;
                f[h2][0] = o[mt][qn][0] * zI[qn];
                f[h2][1] = o[mt][qn][1] * zIb[qn];
                f[h2][2] = o[mt][qn][2] * zI[qn];
                f[h2][3] = o[mt][qn][3] * zIb[qn];
            }
            float e[2][4];
            #pragma unroll
            for (int h2 = 0; h2 < 2; h2++)
                #pragma unroll
                for (int j = 0; j < 4; j++)
                    e[h2][j] = __shfl_xor_sync(0xffffffffu, f[h2][j], 16);

            const int qr0 = b * 2048 + q0 + w * 32 + p * 16 + 2 * lc;
            if (lr < 4) {
                const int k0 = h * 64 + mt * 16 + lr;
                *reinterpret_cast<float4*>(&out[paddrA(qr0, k0, CDIM)]) =
                    make_float4(tf32r(f[0][0]), tf32r(f[1][0]), tf32r(e[0][0]), tf32r(e[1][0]));
                *reinterpret_cast<float4*>(&out[paddrA(qr0 + 1, k0, CDIM)]) =
                    make_float4(tf32r(f[0][1]), tf32r(f[1][1]), tf32r(e[0][1]), tf32r(e[1][1]));
            } else {
                const int kb = h * 64 + mt * 16 + lr + 4;
                *reinterpret_cast<float4*>(&out[paddrA(qr0, kb, CDIM)]) =
                    make_float4(tf32r(e[0][2]), tf32r(e[1][2]), tf32r(f[0][2]), tf32r(f[1][2]));
                *reinterpret_cast<float4*>(&out[paddrA(qr0 + 1, kb, CDIM)]) =
                    make_float4(tf32r(e[0][3]), tf32r(e[1][3]), tf32r(f[0][3]), tf32r(f[1][3]));
            }
        }
    }
}

// ---------------------------------------------------------------------------
// Launch
// ---------------------------------------------------------------------------
extern "C" void kernel_launch(void* const* d_in, const int* in_sizes, int n_in,
                              void* d_out, int out_size)
{
    const float* x        = (const float*)d_in[0];
    const float* c_attn_w = (const float*)d_in[1];
    const float* c_attn_b = (const float*)d_in[2];
    const float* c_proj_w = (const float*)d_in[3];
    const float* c_proj_b = (const float*)d_in[4];
    const float* fc_w     = (const float*)d_in[5];
    const float* fc_b     = (const float*)d_in[6];
    const float* proj_w   = (const float*)d_in[7];
    const float* proj_b   = (const float*)d_in[8];
    const float* ln1_g    = (const float*)d_in[9];
    const float* ln1_b    = (const float*)d_in[10];
    const float* ln2_g    = (const float*)d_in[11];
    const float* ln2_b    = (const float*)d_in[12];

    float *ln1, *qkv, *attn, *x1, *ln2, *hbuf, *w1p, *w2p, *w3p, *w4p;
    cudaGetSymbolAddress((void**)&ln1,  g_ln1);
    cudaGetSymbolAddress((void**)&qkv,  g_qkv);
    cudaGetSymbolAddress((void**)&attn, g_attn);
    cudaGetSymbolAddress((void**)&x1,   g_x1);
    cudaGetSymbolAddress((void**)&ln2,  g_ln2);
    cudaGetSymbolAddress((void**)&hbuf, g_hbuf);
    cudaGetSymbolAddress((void**)&w1p,  g_w1p);
    cudaGetSymbolAddress((void**)&w2p,  g_w2p);
    cudaGetSymbolAddress((void**)&w3p,  g_w3p);
    cudaGetSymbolAddress((void**)&w4p,  g_w4p);

    cudaFuncSetAttribute(mma_gemm, cudaFuncAttributeMaxDynamicSharedMemorySize, GEMM_SMEM);
    cudaFuncSetAttribute(attn_mma, cudaFuncAttributeMaxDynamicSharedMemorySize, ATT_SMEM);

    float* outp = (float*)d_out;

    // 0. prep: weight packing + LN1 in one launch
    prep_kernel<<<10240, 256>>>(c_attn_w, c_proj_w, fc_w, proj_w,
                                w1p, w2p, w3p, w4p,
                                x, ln1_g, ln1_b, ln1);

    // 2. qkv = ln1 @ c_attn_w + b  (natural, tf32-rounded for attention)
    mma_gemm<<<dim3(24, 64), 128, GEMM_SMEM>>>(
        ln1, w1p, c_attn_b, nullptr, qkv, MROWS, 3072, 1024, 0, 0, 1);
    // 3. attention (q-tile 128, heavy CTAs first) -> packed A
    attn_mma<<<dim3(16, 64), 128, ATT_SMEM>>>(qkv, attn);
    // 4. x1 = attn @ c_proj_w + b + x
    mma_gemm<<<dim3(8, 64), 128, GEMM_SMEM>>>(
        attn, w2p, c_proj_b, x, x1, MROWS, 1024, 1024, 0, 0, 0);
    // 5. ln2 = LN(x1) (packed A)
    ln_kernel<<<4096, 256>>>(x1, ln2_g, ln2_b, ln2);
    // 6. h = gelu(ln2 @ fc_w + b) (packed out)
    mma_gemm<<<dim3(32, 64), 128, GEMM_SMEM>>>(
        ln2, w3p, fc_b, nullptr, hbuf, MROWS, 4096, 1024, 1, 1, 0);
    // 7. out = h @ proj_w + b + x1
    mma_gemm<<<dim3(8, 64), 128, GEMM_SMEM>>>(
        hbuf, w4p, proj_b, x1, outp, MROWS, 1024, 4096, 0, 0, 0);
}

// round 16
// speedup vs baseline: 1.1187x; 1.1187x over previous
#include <cuda_runtime.h>
#include <math.h>
#include <stdint.h>

// ---------------------------------------------------------------------------
// B=4, T=2048, C=1024, H=16, HS=64. M = 8192.
// GEMMs + attention on mma.sync.m16n8k8 tf32, fragment-packed operands.
// R16: GEMM occupancy raised to 3 CTAs/SM (12 warps/SM): GSTG=2 (65KB smem),
// __launch_bounds__(128,3), bulk-copy loads (R15). Attention = R13 cp.async.
// ---------------------------------------------------------------------------
#define MROWS 8192
#define CDIM  1024

__device__ float g_ln1 [8192u * 1024];   // packed A
__device__ float g_qkv [8192u * 3072];   // natural, tf32-rounded
__device__ float g_attn[8192u * 1024];   // packed A
__device__ float g_x1  [8192u * 1024];   // natural
__device__ float g_ln2 [8192u * 1024];   // packed A
__device__ float g_hbuf[8192u * 4096];   // packed A
__device__ float g_w1p [1024u * 3072];   // packed B
__device__ float g_w2p [1024u * 1024];
__device__ float g_w3p [1024u * 4096];
__device__ float g_w4p [4096u * 1024];

// ---------------- helpers ----------------
__device__ __forceinline__ float tf32r(float x) {
    uint32_t u;
    asm("cvt.rna.tf32.f32 %0, %1;" : "=r"(u) : "f"(x));
    return __uint_as_float(u);
}
__device__ __forceinline__ uint32_t smem_u32(const void* p) {
    uint32_t a;
    asm("{ .reg .u64 t; cvta.to.shared.u64 t, %1; cvt.u32.u64 %0, t; }"
        : "=r"(a) : "l"(p));
    return a;
}
#define CP_ASYNC16(dst, src) \
    asm volatile("cp.async.cg.shared.global [%0], [%1], 16;" :: "r"(dst), "l"(src))
#define CP_COMMIT() asm volatile("cp.async.commit_group;" ::: "memory")
#define CP_WAIT0()  asm volatile("cp.async.wait_group 0;"  ::: "memory")
#define CP_WAIT1()  asm volatile("cp.async.wait_group 1;"  ::: "memory")

__device__ __forceinline__ void bulk_g2s(uint32_t dst, const void* src,
                                         uint32_t bytes, uint32_t mbar) {
    asm volatile(
        "cp.async.bulk.shared::cluster.global.mbarrier::complete_tx::bytes [%0], [%1], %2, [%3];"
        :: "r"(dst), "l"(src), "r"(bytes), "r"(mbar) : "memory");
}
#define MBARRIER_INIT(addr, cnt) \
    asm volatile("mbarrier.init.shared.b64 [%0], %1;" :: "r"(addr), "r"(cnt) : "memory")
#define MBARRIER_EXPECT_TX(addr, tx) \
    asm volatile("mbarrier.arrive.expect_tx.shared.b64 _, [%0], %1;" :: "r"(addr), "r"(tx) : "memory")
#define MBARRIER_WAIT_PARITY(addr, par) do { \
    uint32_t _m = (addr); uint32_t _p = (par); uint32_t _d; \
    asm volatile("{ .reg .pred p; mbarrier.try_wait.parity.acquire.cta.shared::cta.b64 p, [%1], %2; selp.b32 %0, 1, 0, p; }" \
        : "=r"(_d) : "r"(_m), "r"(_p) : "memory"); \
    if (!_d) { \
        asm volatile("{ .reg .pred P1; WL_%=: mbarrier.try_wait.parity.acquire.cta.shared::cta.b64 P1, [%0], %1, 0x989680; @P1 bra.uni WD_%=; bra.uni WL_%=; WD_%=: }" \
            :: "r"(_m), "r"(_p) : "memory"); \
    } } while (0)
#define FENCE_PROXY_ASYNC() asm volatile("fence.proxy.async.shared::cta;" ::: "memory")

__device__ __forceinline__ void mma_tf32(float c[4], uint32_t a0, uint32_t a1,
                                         uint32_t a2, uint32_t a3,
                                         uint32_t b0, uint32_t b1) {
    asm volatile(
        "mma.sync.aligned.m16n8k8.row.col.f32.tf32.tf32.f32 "
        "{%0,%1,%2,%3}, {%4,%5,%6,%7}, {%8,%9}, {%0,%1,%2,%3};"
        : "+f"(c[0]), "+f"(c[1]), "+f"(c[2]), "+f"(c[3])
        : "r"(a0), "r"(a1), "r"(a2), "r"(a3), "r"(b0), "r"(b1));
}

__device__ __forceinline__ float gelu_f(float x) {
    float x3 = x * x * x;
    return 0.5f * x * (1.0f + tanhf(0.7978845608028654f * (x + 0.044715f * x3)));
}

// Packed-A address (float index) for element (m,k) of an [M,K] A operand.
__device__ __forceinline__ size_t paddrA(int m, int k, int K) {
    const int mb = m >> 7, rm = m & 127;
    const int wm = rm >> 5, mt = (rm >> 4) & 1, lr = rm & 7, ah = (rm >> 3) & 1;
    const int kt = k >> 5, kk = (k >> 3) & 3, lc = k & 3, kh = (k >> 2) & 1;
    const int lane = lr * 4 + lc;
    const int reg  = ah + 2 * kh;
    return ((size_t)mb * (K >> 5) + kt) * 4096 +
           ((((kk * 4 + wm) * 2 + mt) * 32 + lane) * 4 + reg);
}
// Packed-B address (float index) for element (n,k) of W[K,N] viewed as [N,K].
__device__ __forceinline__ size_t paddrB(int n, int k, int K) {
    const int nb = n >> 7, rn = n & 127;
    const int wn = (rn >> 6) & 1, nt = (rn >> 3) & 7, n8 = rn & 7;
    const int kt = k >> 5, kk = (k >> 3) & 3, kh = (k >> 2) & 1;
    const int lane = n8 * 4 + (k & 3);
    return ((size_t)nb * (K >> 5) + kt) * 4096 +
           ((((kk * 2 + wn) * 8 + nt) * 32 + lane) * 2 + kh);
}

// ---------------------------------------------------------------------------
// LN body (shared by prep_kernel and ln_kernel)
// ---------------------------------------------------------------------------
__device__ __forceinline__ void ln_body(
    const float* __restrict__ x, const float* __restrict__ g,
    const float* __restrict__ b, float* __restrict__ o, int p, int tid)
{
    const int m0 = (p >> 3) * 16 + (p & 7);
    const int m1 = m0 + 8;
    const int k0 = ((tid >> 2) << 3) + (tid & 3);
    const int k1 = k0 + 512;

    const float* x0 = x + (size_t)m0 * CDIM;
    const float* x1 = x + (size_t)m1 * CDIM;
    const float a00 = x0[k0], a01 = x0[k0 + 4], a02 = x0[k1], a03 = x0[k1 + 4];
    const float a10 = x1[k0], a11 = x1[k0 + 4], a12 = x1[k1], a13 = x1[k1 + 4];

    float s0 = a00 + a01 + a02 + a03;
    float q0 = a00 * a00 + a01 * a01 + a02 * a02 + a03 * a03;
    float s1 = a10 + a11 + a12 + a13;
    float q1 = a10 * a10 + a11 * a11 + a12 * a12 + a13 * a13;

    #pragma unroll
    for (int off = 16; off > 0; off >>= 1) {
        s0 += __shfl_xor_sync(0xffffffffu, s0, off);
        q0 += __shfl_xor_sync(0xffffffffu, q0, off);
        s1 += __shfl_xor_sync(0xffffffffu, s1, off);
        q1 += __shfl_xor_sync(0xffffffffu, q1, off);
    }
    __shared__ float red[4][8];
    const int wid = tid >> 5;
    if ((tid & 31) == 0) {
        red[0][wid] = s0; red[1][wid] = q0; red[2][wid] = s1; red[3][wid] = q1;
    }
    __syncthreads();
    float ts0 = 0.f, tq0 = 0.f, ts1 = 0.f, tq1 = 0.f;
    #pragma unroll
    for (int w = 0; w < 8; w++) {
        ts0 += red[0][w]; tq0 += red[1][w]; ts1 += red[2][w]; tq1 += red[3][w];
    }

    const float mu0 = ts0 * (1.0f / CDIM);
    const float mu1 = ts1 * (1.0f / CDIM);
    const float r0 = rsqrtf(tq0 * (1.0f / CDIM) - mu0 * mu0 + 1e-5f);
    const float r1 = rsqrtf(tq1 * (1.0f / CDIM) - mu1 * mu1 + 1e-5f);

    #pragma unroll
    for (int gi = 0; gi < 2; gi++) {
        const int k = gi ? k1 : k0;
        const float ga = __ldg(&g[k]), gb = __ldg(&g[k + 4]);
        const float ba = __ldg(&b[k]), bb = __ldg(&b[k + 4]);
        const float xa0 = gi ? a02 : a00, xa1 = gi ? a03 : a01;
        const float xb0 = gi ? a12 : a10, xb1 = gi ? a13 : a11;
        *reinterpret_cast<float4*>(&o[paddrA(m0, k, CDIM)]) = make_float4(
            tf32r((xa0 - mu0) * r0 * ga + ba),
            tf32r((xb0 - mu1) * r1 * ga + ba),
            tf32r((xa1 - mu0) * r0 * gb + bb),
            tf32r((xb1 - mu1) * r1 * gb + bb));
    }
}

__device__ __forceinline__ void wprep_body(
    const float* __restrict__ W, float* __restrict__ O,
    int K, int N, int idx)
{
    const int n  = idx % N;
    const int kb = (idx / N) * 8;
    float v[8];
    #pragma unroll
    for (int i = 0; i < 8; i++)
        v[i] = tf32r(__ldg(&W[(size_t)(kb + i) * N + n]));
    float4* p = reinterpret_cast<float4*>(&O[paddrB(n, kb, K)]);
    p[0] = make_float4(v[0], v[4], v[1], v[5]);
    p[1] = make_float4(v[2], v[6], v[3], v[7]);
}

// ---------------------------------------------------------------------------
// prep_kernel: weights pack (blocks 0..6143) + LN1 (blocks 6144..10239)
// ---------------------------------------------------------------------------
__global__ __launch_bounds__(256) void prep_kernel(
    const float* __restrict__ w1, const float* __restrict__ w2,
    const float* __restrict__ w3, const float* __restrict__ w4,
    float* __restrict__ o1, float* __restrict__ o2,
    float* __restrict__ o3, float* __restrict__ o4,
    const float* __restrict__ x, const float* __restrict__ ln1_g,
    const float* __restrict__ ln1_b, float* __restrict__ ln1_o)
{
    const int bid = blockIdx.x;
    const int tid = threadIdx.x;
    if (bid < 1536)
        wprep_body(w1, o1, 1024, 3072, bid * 256 + tid);
    else if (bid < 2048)
        wprep_body(w2, o2, 1024, 1024, (bid - 1536) * 256 + tid);
    else if (bid < 4096)
        wprep_body(w3, o3, 1024, 4096, (bid - 2048) * 256 + tid);
    else if (bid < 6144)
        wprep_body(w4, o4, 4096, 1024, (bid - 4096) * 256 + tid);
    else
        ln_body(x, ln1_g, ln1_b, ln1_o, bid - 6144, tid);
}

__global__ __launch_bounds__(256) void ln_kernel(
    const float* __restrict__ x, const float* __restrict__ g,
    const float* __restrict__ b, float* __restrict__ o)
{
    ln_body(x, g, b, o, blockIdx.x, threadIdx.x);
}

// ---------------------------------------------------------------------------
// tf32 mma.sync GEMM, fragment-packed operands.
// 128 threads, 4 warps (2m x 2n), warp tile 64x64.
// GSTG=2 (double buffer), 3 CTAs/SM (12 warps/SM), bulk-copy loads.
// Smem: [2 x 8B mbarriers][pad to 1024][2 x 32KB stages] = 66560 B.
// Pipeline: WAIT(t) -> sync -> ISSUE(t+1) -> compute(t).
// ---------------------------------------------------------------------------
#define GSTG 2
#define STG_FLOATS 8192
#define GEMM_SMEM (1024 + GSTG * STG_FLOATS * 4)

__global__ __launch_bounds__(128, 3) void mma_gemm(
    const float* __restrict__ Apk, const float* __restrict__ Bpk,
    const float* __restrict__ bias, const float* __restrict__ resid,
    float* __restrict__ C, int M, int N, int K, int act, int pack_out,
    int round_out)
{
    extern __shared__ float sm[];
    const uint32_t sb = smem_u32(sm);
    const uint32_t tiles_u = sb + 1024;
    float* tiles_f = sm + 256;

    const int tid  = threadIdx.x;
    const int wid  = tid >> 5;
    const int lane = tid & 31;
    const int wm = wid & 1;
    const int wn = wid >> 1;
    const int bm = blockIdx.y << 7;
    const int bn = blockIdx.x << 7;
    const int lr = lane >> 2;
    const int lc = lane & 3;

    const int nk = K >> 5;
    const char* abase = (const char*)Apk + (size_t)blockIdx.y * nk * 16384;
    const char* bbase = (const char*)Bpk + (size_t)blockIdx.x * nk * 16384;

    if (tid == 0) {
        MBARRIER_INIT(sb,     1);
        MBARRIER_INIT(sb + 8, 1);
        FENCE_PROXY_ASYNC();
    }
    __syncthreads();

    float acc[4][8][4];
    #pragma unroll
    for (int at = 0; at < 4; at++)
        #pragma unroll
        for (int nt = 0; nt < 8; nt++)
            #pragma unroll
            for (int j = 0; j < 4; j++) acc[at][nt][j] = 0.f;

    #define ISSUEB(t) do { \
        if ((t) < nk && tid == 0) { \
            const uint32_t _m = sb + 8 * ((t) & 1); \
            const uint32_t _d = tiles_u + ((t) & 1) * 32768; \
            MBARRIER_EXPECT_TX(_m, 32768u); \
            bulk_g2s(_d,         abase + (size_t)(t) * 16384, 16384u, _m); \
            bulk_g2s(_d + 16384, bbase + (size_t)(t) * 16384, 16384u, _m); \
        } \
    } while (0)

    ISSUEB(0);

    for (int t = 0; t < nk; t++) {
        MBARRIER_WAIT_PARITY(sb + 8 * (t & 1), (uint32_t)((t >> 1) & 1));
        __syncthreads();   // all warps retired reads of stage (t-1)&1
        ISSUEB(t + 1);     // overwrites stage (t+1)&1 == (t-1)&1 — safe

        const float* Ab = tiles_f + (t & 1) * STG_FLOATS;
        const float* Bb = Ab + 4096;
        #pragma unroll
        for (int kk = 0; kk < 4; kk++) {
            uint4 a[4];
            #pragma unroll
            for (int at = 0; at < 4; at++)
                a[at] = *reinterpret_cast<const uint4*>(
                    Ab + ((kk * 4 + wm * 2 + (at >> 1)) * 2 + (at & 1)) * 128 + lane * 4);
            const float* bq = Bb + (kk * 2 + wn) * 512 + lane * 2;
            #pragma unroll
            for (int nt = 0; nt < 8; nt++) {
                const uint2 bv = *reinterpret_cast<const uint2*>(bq + nt * 64);
                #pragma unroll
                for (int at = 0; at < 4; at++)
                    mma_tf32(acc[at][nt], a[at].x, a[at].y, a[at].z, a[at].w,
                             bv.x, bv.y);
            }
        }
    }

    #pragma unroll
    for (int at = 0; at < 4; at++) {
        const int r0 = bm + wm * 64 + (at >> 1) * 32 + (at & 1) * 16 + lr;
        const int r1 = r0 + 8;
        #pragma unroll
        for (int nt = 0; nt < 8; nt++) {
            const int col = bn + wn * 64 + nt * 8 + lc * 2;
            const float bb0 = __ldg(&bias[col]);
            const float bb1 = __ldg(&bias[col + 1]);
            float v0 = acc[at][nt][0] + bb0;
            float v1 = acc[at][nt][1] + bb1;
            float v2 = acc[at][nt][2] + bb0;
            float v3 = acc[at][nt][3] + bb1;
            if (act) {
                v0 = gelu_f(v0); v1 = gelu_f(v1);
                v2 = gelu_f(v2); v3 = gelu_f(v3);
            }
            if (pack_out) {
                const float u0 = __shfl_xor_sync(0xffffffffu, v0, 2);
                const float u1 = __shfl_xor_sync(0xffffffffu, v1, 2);
                const float u2 = __shfl_xor_sync(0xffffffffu, v2, 2);
                const float u3 = __shfl_xor_sync(0xffffffffu, v3, 2);
                if (lc < 2) {
                    *reinterpret_cast<float4*>(&C[paddrA(r0, col, N)]) =
                        make_float4(tf32r(v0), tf32r(v2), tf32r(u0), tf32r(u2));
                } else {
                    const int colo = col - 3;
                    *reinterpret_cast<float4*>(&C[paddrA(r0, colo, N)]) =
                        make_float4(tf32r(u1), tf32r(u3), tf32r(v1), tf32r(v3));
                }
            } else {
                const size_t o0 = (size_t)r0 * N + col;
                const size_t o1 = (size_t)r1 * N + col;
                if (resid) {
                    const float2 q0 = *reinterpret_cast<const float2*>(&resid[o0]);
                    const float2 q1 = *reinterpret_cast<const float2*>(&resid[o1]);
                    v0 += q0.x; v1 += q0.y; v2 += q1.x; v3 += q1.y;
                }
                if (round_out) {
                    v0 = tf32r(v0); v1 = tf32r(v1); v2 = tf32r(v2); v3 = tf32r(v3);
                }
                *reinterpret_cast<float2*>(&C[o0]) = make_float2(v0, v1);
                *reinterpret_cast<float2*>(&C[o1]) = make_float2(v2, v3);
            }
        }
    }
}

// ---------------------------------------------------------------------------
// Flash attention on mma.sync tf32, causal — R13 cp.async version.
// CTA q-tile 128 (4 warps x 32 q). Single barrier per iteration.
// ---------------------------------------------------------------------------
#define AST_K 68
#define AST_V 72
#define ATT_QOFF 0
#define ATT_KOFF(b) (8704 + (b) * 4352)
#define ATT_VOFF(b) (17408 + (b) * 4608)
#define ATT_SMEM (26624 * 4)

__global__ __launch_bounds__(128, 2) void attn_mma(
    const float* __restrict__ qkv, float* __restrict__ out)
{
    extern __shared__ float sm[];
    const uint32_t sb = smem_u32(sm);
    const int tid = threadIdx.x;
    const int w = tid >> 5, lane = tid & 31;
    const int lr = lane >> 2, lc = lane & 3;
    const int qt = (int)gridDim.x - 1 - (int)blockIdx.x;
    const int bh = blockIdx.y;
    const int b = bh >> 4, h = bh & 15;
    const int q0 = qt * 128;
    const float* basep = qkv + (size_t)b * 2048 * 3072 + (size_t)h * 64;

    #pragma unroll
    for (int i = 0; i < 16; i++) {
        const int idx = tid + i * 128, row = idx >> 4, ch = idx & 15;
        CP_ASYNC16(sb + (uint32_t)(ATT_QOFF + row * AST_K + ch * 4) * 4,
                   basep + (size_t)(q0 + row) * 3072 + ch * 4);
    }
    CP_COMMIT();

    #define ISSUE_KV(kt_, bb) do { \
        const float* _k = basep + (size_t)((kt_) * 64) * 3072 + 1024; \
        _Pragma("unroll") \
        for (int _i = 0; _i < 8; _i++) { \
            const int _idx = tid + _i * 128, _r = _idx >> 4, _c = _idx & 15; \
            CP_ASYNC16(sb + (uint32_t)(ATT_KOFF(bb) + _r * AST_K + _c * 4) * 4, \
                       _k + (size_t)_r * 3072 + _c * 4); \
            CP_ASYNC16(sb + (uint32_t)(ATT_VOFF(bb) + _r * AST_V + _c * 4) * 4, \
                       _k + 1024 + (size_t)_r * 3072 + _c * 4); \
        } \
        CP_COMMIT(); \
    } while (0)

    ISSUE_KV(0, 0);

    CP_WAIT1();
    __syncthreads();

    float qa[2][8][4];
    {
        const float* Qs = sm + ATT_QOFF;
        #pragma unroll
        for (int mt2 = 0; mt2 < 2; mt2++) {
            const int r0 = w * 32 + mt2 * 16 + lr;
            #pragma unroll
            for (int kk = 0; kk < 8; kk++) {
                qa[mt2][kk][0] = 0.125f * Qs[r0 * AST_K + kk * 8 + lc];
                qa[mt2][kk][1] = 0.125f * Qs[(r0 + 8) * AST_K + kk * 8 + lc];
                qa[mt2][kk][2] = 0.125f * Qs[r0 * AST_K + kk * 8 + lc + 4];
                qa[mt2][kk][3] = 0.125f * Qs[(r0 + 8) * AST_K + kk * 8 + lc + 4];
            }
        }
    }
    __syncthreads();

    float* Pw = sm + ATT_QOFF + w * 2048;

    float m[2][2], l[2][2];
    #pragma unroll
    for (int i = 0; i < 2; i++)
        #pragma unroll
        for (int j2 = 0; j2 < 2; j2++) { m[i][j2] = -1e30f; l[i][j2] = 0.f; }

    float o[4][4][4];
    #pragma unroll
    for (int mt = 0; mt < 4; mt++)
        #pragma unroll
        for (int qn = 0; qn < 4; qn++)
            #pragma unroll
            for (int j = 0; j < 4; j++) o[mt][qn][j] = 0.f;

    const int ktmax = 2 * qt + 1;
    for (int kt = 0; kt <= ktmax; kt++) {
        const int buf = kt & 1;
        CP_WAIT0();
        __syncthreads();
        if (kt < ktmax) ISSUE_KV(kt + 1, buf ^ 1);

        if (64 * kt <= q0 + w * 32 + 31) {
            const float* Ks = sm + ATT_KOFF(buf);
            const float* Vs = sm + ATT_VOFF(buf);

            float s[2][8][4];
            #pragma unroll
            for (int mt2 = 0; mt2 < 2; mt2++)
                #pragma unroll
                for (int nt = 0; nt < 8; nt++)
                    #pragma unroll
                    for (int j = 0; j < 4; j++) s[mt2][nt][j] = 0.f;

            #pragma unroll
            for (int kk = 0; kk < 8; kk++) {
                #pragma unroll
                for (int nt = 0; nt < 8; nt++) {
                    const uint32_t b0 = __float_as_uint(Ks[(nt * 8 + lr) * AST_K + kk * 8 + lc]);
                    const uint32_t b1 = __float_as_uint(Ks[(nt * 8 + lr) * AST_K + kk * 8 + lc + 4]);
                    mma_tf32(s[0][nt],
                             __float_as_uint(qa[0][kk][0]), __float_as_uint(qa[0][kk][1]),
                             __float_as_uint(qa[0][kk][2]), __float_as_uint(qa[0][kk][3]),
                             b0, b1);
                    mma_tf32(s[1][nt],
                             __float_as_uint(qa[1][kk][0]), __float_as_uint(qa[1][kk][1]),
                             __float_as_uint(qa[1][kk][2]), __float_as_uint(qa[1][kk][3]),
                             b0, b1);
                }
            }

            #pragma unroll
            for (int mt2 = 0; mt2 < 2; mt2++) {
                const int rbase = q0 + w * 32 + mt2 * 16;
                if (64 * kt + 63 > rbase) {
                    #pragma unroll
                    for (int nt = 0; nt < 8; nt++) {
                        const int c = 64 * kt + nt * 8 + 2 * lc;
                        if (c     > rbase + lr)     s[mt2][nt][0] = -1e30f;
                        if (c + 1 > rbase + lr)     s[mt2][nt][1] = -1e30f;
                        if (c     > rbase + lr + 8) s[mt2][nt][2] = -1e30f;
                        if (c + 1 > rbase + lr + 8) s[mt2][nt][3] = -1e30f;
                    }
                }
            }

            float al[2][2];
            #pragma unroll
            for (int mt2 = 0; mt2 < 2; mt2++) {
                float mx0 = -1e30f, mx1 = -1e30f;
                #pragma unroll
                for (int nt = 0; nt < 8; nt++) {
                    mx0 = fmaxf(mx0, fmaxf(s[mt2][nt][0], s[mt2][nt][1]));
                    mx1 = fmaxf(mx1, fmaxf(s[mt2][nt][2], s[mt2][nt][3]));
                }
                mx0 = fmaxf(mx0, __shfl_xor_sync(0xffffffffu, mx0, 1));
                mx0 = fmaxf(mx0, __shfl_xor_sync(0xffffffffu, mx0, 2));
                mx1 = fmaxf(mx1, __shfl_xor_sync(0xffffffffu, mx1, 1));
                mx1 = fmaxf(mx1, __shfl_xor_sync(0xffffffffu, mx1, 2));

                const float mn0 = fmaxf(m[mt2][0], mx0);
                const float mn1 = fmaxf(m[mt2][1], mx1);
                al[mt2][0] = __expf(m[mt2][0] - mn0);
                al[mt2][1] = __expf(m[mt2][1] - mn1);
                m[mt2][0] = mn0; m[mt2][1] = mn1;

                float sum0 = 0.f, sum1 = 0.f;
                #pragma unroll
                for (int nt = 0; nt < 8; nt++) {
                    s[mt2][nt][0] = __expf(s[mt2][nt][0] - mn0); sum0 += s[mt2][nt][0];
                    s[mt2][nt][1] = __expf(s[mt2][nt][1] - mn0); sum0 += s[mt2][nt][1];
                    s[mt2][nt][2] = __expf(s[mt2][nt][2] - mn1); sum1 += s[mt2][nt][2];
                    s[mt2][nt][3] = __expf(s[mt2][nt][3] - mn1); sum1 += s[mt2][nt][3];
                }
                sum0 += __shfl_xor_sync(0xffffffffu, sum0, 1);
                sum0 += __shfl_xor_sync(0xffffffffu, sum0, 2);
                sum1 += __shfl_xor_sync(0xffffffffu, sum1, 1);
                sum1 += __shfl_xor_sync(0xffffffffu, sum1, 2);
                l[mt2][0] = l[mt2][0] * al[mt2][0] + sum0;
                l[mt2][1] = l[mt2][1] * al[mt2][1] + sum1;
            }

            #pragma unroll
            for (int qn = 0; qn < 4; qn++) {
                const float zA  = __shfl_sync(0xffffffffu, al[qn >> 1][qn & 1], 8 * lc);
                const float zAb = __shfl_sync(0xffffffffu, al[qn >> 1][qn & 1], 8 * lc + 4);
                #pragma unroll
                for (int mt = 0; mt < 4; mt++) {
                    o[mt][qn][0] *= zA;  o[mt][qn][1] *= zAb;
                    o[mt][qn][2] *= zA;  o[mt][qn][3] *= zAb;
                }
            }

            __syncwarp();
            {
                const int c0c = 2 * lc, c1c = 2 * lc + 1;
                const int ln0 = lr * 4 + (c0c & 3), rg0 = (c0c & 4) >> 2;
                const int ln1 = lr * 4 + (c1c & 3), rg1 = (c1c & 4) >> 2;
                #pragma unroll
                for (int mt2 = 0; mt2 < 2; mt2++) {
                    #pragma unroll
                    for (int nt = 0; nt < 8; nt++) {
                        const int q0n = mt2 * 2;
                        Pw[(nt * 4 + q0n + 0) * 64 + ln0 * 2 + rg0] = tf32r(s[mt2][nt][0]);
                        Pw[(nt * 4 + q0n + 0) * 64 + ln1 * 2 + rg1] = tf32r(s[mt2][nt][1]);
                        Pw[(nt * 4 + q0n + 1) * 64 + ln0 * 2 + rg0] = tf32r(s[mt2][nt][2]);
                        Pw[(nt * 4 + q0n + 1) * 64 + ln1 * 2 + rg1] = tf32r(s[mt2][nt][3]);
                    }
                }
            }
            __syncwarp();

            #pragma unroll
            for (int kk2 = 0; kk2 < 8; kk2++) {
                uint2 bp[4];
                #pragma unroll
                for (int qn = 0; qn < 4; qn++)
                    bp[qn] = *reinterpret_cast<const uint2*>(
                        Pw + (kk2 * 4 + qn) * 64 + lane * 2);
                #pragma unroll
                for (int mt = 0; mt < 4; mt++) {
                    const uint32_t a0 = __float_as_uint(Vs[(kk2 * 8 + lc) * AST_V + mt * 16 + lr]);
                    const uint32_t a1 = __float_as_uint(Vs[(kk2 * 8 + lc) * AST_V + mt * 16 + lr + 8]);
                    const uint32_t a2 = __float_as_uint(Vs[(kk2 * 8 + lc + 4) * AST_V + mt * 16 + lr]);
                    const uint32_t a3 = __float_as_uint(Vs[(kk2 * 8 + lc + 4) * AST_V + mt * 16 + lr + 8]);
                    #pragma unroll
                    for (int qn = 0; qn < 4; qn++)
                        mma_tf32(o[mt][qn], a0, a1, a2, a3, bp[qn].x, bp[qn].y);
                }
            }
        }
    }

    float zI[4], zIb[4];
    #pragma unroll
    for (int qn = 0; qn < 4; qn++) {
        const float inv = 1.0f / l[qn >> 1][qn & 1];
        zI[qn]  = __shfl_sync(0xffffffffu, inv, 8 * lc);
        zIb[qn] = __shfl_sync(0xffffffffu, inv, 8 * lc + 4);
    }

    #pragma unroll
    for (int mt = 0; mt < 4; mt++) {
        #pragma unroll
        for (int p = 0; p < 2; p++) {
            float f[2][4];
            #pragma unroll
            for (int h2 = 0; h2 < 2; h2++) {
                const int qn = 2 * p + h2;
                f[h2][0] = o[mt][qn][0] * zI[qn];
                f[h2][1] = o[mt][qn][1] * zIb[qn];
                f[h2][2] = o[mt][qn][2] * zI[qn];
                f[h2][3] = o[mt][qn][3] * zIb[qn];
            }
            float e[2][4];
            #pragma unroll
            for (int h2 = 0; h2 < 2; h2++)
                #pragma unroll
                for (int j = 0; j < 4; j++)
                    e[h2][j] = __shfl_xor_sync(0xffffffffu, f[h2][j], 16);

            const int qr0 = b * 2048 + q0 + w * 32 + p * 16 + 2 * lc;
            if (lr < 4) {
                const int k0 = h * 64 + mt * 16 + lr;
                *reinterpret_cast<float4*>(&out[paddrA(qr0, k0, CDIM)]) =
                    make_float4(tf32r(f[0][0]), tf32r(f[1][0]), tf32r(e[0][0]), tf32r(e[1][0]));
                *reinterpret_cast<float4*>(&out[paddrA(qr0 + 1, k0, CDIM)]) =
                    make_float4(tf32r(f[0][1]), tf32r(f[1][1]), tf32r(e[0][1]), tf32r(e[1][1]));
            } else {
                const int kb = h * 64 + mt * 16 + lr + 4;
                *reinterpret_cast<float4*>(&out[paddrA(qr0, kb, CDIM)]) =
                    make_float4(tf32r(e[0][2]), tf32r(e[1][2]), tf32r(f[0][2]), tf32r(f[1][2]));
                *reinterpret_cast<float4*>(&out[paddrA(qr0 + 1, kb, CDIM)]) =
                    make_float4(tf32r(e[0][3]), tf32r(e[1][3]), tf32r(f[0][3]), tf32r(f[1][3]));
            }
        }
    }
}

// ---------------------------------------------------------------------------
// Launch
// ---------------------------------------------------------------------------
extern "C" void kernel_launch(void* const* d_in, const int* in_sizes, int n_in,
                              void* d_out, int out_size)
{
    const float* x        = (const float*)d_in[0];
    const float* c_attn_w = (const float*)d_in[1];
    const float* c_attn_b = (const float*)d_in[2];
    const float* c_proj_w = (const float*)d_in[3];
    const float* c_proj_b = (const float*)d_in[4];
    const float* fc_w     = (const float*)d_in[5];
    const float* fc_b     = (const float*)d_in[6];
    const float* proj_w   = (const float*)d_in[7];
    const float* proj_b   = (const float*)d_in[8];
    const float* ln1_g    = (const float*)d_in[9];
    const float* ln1_b    = (const float*)d_in[10];
    const float* ln2_g    = (const float*)d_in[11];
    const float* ln2_b    = (const float*)d_in[12];

    float *ln1, *qkv, *attn, *x1, *ln2, *hbuf, *w1p, *w2p, *w3p, *w4p;
    cudaGetSymbolAddress((void**)&ln1,  g_ln1);
    cudaGetSymbolAddress((void**)&qkv,  g_qkv);
    cudaGetSymbolAddress((void**)&attn, g_attn);
    cudaGetSymbolAddress((void**)&x1,   g_x1);
    cudaGetSymbolAddress((void**)&ln2,  g_ln2);
    cudaGetSymbolAddress((void**)&hbuf, g_hbuf);
    cudaGetSymbolAddress((void**)&w1p,  g_w1p);
    cudaGetSymbolAddress((void**)&w2p,  g_w2p);
    cudaGetSymbolAddress((void**)&w3p,  g_w3p);
    cudaGetSymbolAddress((void**)&w4p,  g_w4p);

    cudaFuncSetAttribute(mma_gemm, cudaFuncAttributeMaxDynamicSharedMemorySize, GEMM_SMEM);
    cudaFuncSetAttribute(attn_mma, cudaFuncAttributeMaxDynamicSharedMemorySize, ATT_SMEM);

    float* outp = (float*)d_out;

    // 0. prep: weight packing + LN1 in one launch
    prep_kernel<<<10240, 256>>>(c_attn_w, c_proj_w, fc_w, proj_w,
                                w1p, w2p, w3p, w4p,
                                x, ln1_g, ln1_b, ln1);

    // 2. qkv = ln1 @ c_attn_w + b  (natural, tf32-rounded for attention)
    mma_gemm<<<dim3(24, 64), 128, GEMM_SMEM>>>(
        ln1, w1p, c_attn_b, nullptr, qkv, MROWS, 3072, 1024, 0, 0, 1);
    // 3. attention (q-tile 128, heavy CTAs first) -> packed A
    attn_mma<<<dim3(16, 64), 128, ATT_SMEM>>>(qkv, attn);
    // 4. x1 = attn @ c_proj_w + b + x
    mma_gemm<<<dim3(8, 64), 128, GEMM_SMEM>>>(
        attn, w2p, c_proj_b, x, x1, MROWS, 1024, 1024, 0, 0, 0);
    // 5. ln2 = LN(x1) (packed A)
    ln_kernel<<<4096, 256>>>(x1, ln2_g, ln2_b, ln2);
    // 6. h = gelu(ln2 @ fc_w + b) (packed out)
    mma_gemm<<<dim3(32, 64), 128, GEMM_SMEM>>>(
        ln2, w3p, fc_b, nullptr, hbuf, MROWS, 4096, 1024, 1, 1, 0);
    // 7. out = h @ proj_w + b + x1
    mma_gemm<<<dim3(8, 64), 128, GEMM_SMEM>>>(
        hbuf, w4p, proj_b, x1, outp, MROWS, 1024, 4096, 0, 0, 0);
}

// round 17
// speedup vs baseline: 1.1985x; 1.0713x over previous
#include <cuda_runtime.h>
#include <math.h>
#include <stdint.h>

// ---------------------------------------------------------------------------
// B=4, T=2048, C=1024, H=16, HS=64. M = 8192.
// GEMMs + attention on mma.sync.m16n8k8 tf32, fragment-packed operands.
// R17: GEMM CTA tile 64x128 (4 warps, warp tile 32x64), GSTG=2, bulk loads,
// 4 CTAs/SM (16 warps/SM). Kills c_proj/proj wave-quantization (58%->86%).
// Per-element k-order unchanged -> bitwise identical to R16.
// ---------------------------------------------------------------------------
#define MROWS 8192
#define CDIM  1024

__device__ float g_ln1 [8192u * 1024];   // packed A
__device__ float g_qkv [8192u * 3072];   // natural, tf32-rounded
__device__ float g_attn[8192u * 1024];   // packed A
__device__ float g_x1  [8192u * 1024];   // natural
__device__ float g_ln2 [8192u * 1024];   // packed A
__device__ float g_hbuf[8192u * 4096];   // packed A
__device__ float g_w1p [1024u * 3072];   // packed B
__device__ float g_w2p [1024u * 1024];
__device__ float g_w3p [1024u * 4096];
__device__ float g_w4p [4096u * 1024];

// ---------------- helpers ----------------
__device__ __forceinline__ float tf32r(float x) {
    uint32_t u;
    asm("cvt.rna.tf32.f32 %0, %1;" : "=r"(u) : "f"(x));
    return __uint_as_float(u);
}
__device__ __forceinline__ uint32_t smem_u32(const void* p) {
    uint32_t a;
    asm("{ .reg .u64 t; cvta.to.shared.u64 t, %1; cvt.u32.u64 %0, t; }"
        : "=r"(a) : "l"(p));
    return a;
}
#define CP_ASYNC16(dst, src) \
    asm volatile("cp.async.cg.shared.global [%0], [%1], 16;" :: "r"(dst), "l"(src))
#define CP_COMMIT() asm volatile("cp.async.commit_group;" ::: "memory")
#define CP_WAIT0()  asm volatile("cp.async.wait_group 0;"  ::: "memory")
#define CP_WAIT1()  asm volatile("cp.async.wait_group 1;"  ::: "memory")

__device__ __forceinline__ void bulk_g2s(uint32_t dst, const void* src,
                                         uint32_t bytes, uint32_t mbar) {
    asm volatile(
        "cp.async.bulk.shared::cluster.global.mbarrier::complete_tx::bytes [%0], [%1], %2, [%3];"
        :: "r"(dst), "l"(src), "r"(bytes), "r"(mbar) : "memory");
}
#define MBARRIER_INIT(addr, cnt) \
    asm volatile("mbarrier.init.shared.b64 [%0], %1;" :: "r"(addr), "r"(cnt) : "memory")
#define MBARRIER_EXPECT_TX(addr, tx) \
    asm volatile("mbarrier.arrive.expect_tx.shared.b64 _, [%0], %1;" :: "r"(addr), "r"(tx) : "memory")
#define MBARRIER_WAIT_PARITY(addr, par) do { \
    uint32_t _m = (addr); uint32_t _p = (par); uint32_t _d; \
    asm volatile("{ .reg .pred p; mbarrier.try_wait.parity.acquire.cta.shared::cta.b64 p, [%1], %2; selp.b32 %0, 1, 0, p; }" \
        : "=r"(_d) : "r"(_m), "r"(_p) : "memory"); \
    if (!_d) { \
        asm volatile("{ .reg .pred P1; WL_%=: mbarrier.try_wait.parity.acquire.cta.shared::cta.b64 P1, [%0], %1, 0x989680; @P1 bra.uni WD_%=; bra.uni WL_%=; WD_%=: }" \
            :: "r"(_m), "r"(_p) : "memory"); \
    } } while (0)
#define FENCE_PROXY_ASYNC() asm volatile("fence.proxy.async.shared::cta;" ::: "memory")

__device__ __forceinline__ void mma_tf32(float c[4], uint32_t a0, uint32_t a1,
                                         uint32_t a2, uint32_t a3,
                                         uint32_t b0, uint32_t b1) {
    asm volatile(
        "mma.sync.aligned.m16n8k8.row.col.f32.tf32.tf32.f32 "
        "{%0,%1,%2,%3}, {%4,%5,%6,%7}, {%8,%9}, {%0,%1,%2,%3};"
        : "+f"(c[0]), "+f"(c[1]), "+f"(c[2]), "+f"(c[3])
        : "r"(a0), "r"(a1), "r"(a2), "r"(a3), "r"(b0), "r"(b1));
}

__device__ __forceinline__ float gelu_f(float x) {
    float x3 = x * x * x;
    return 0.5f * x * (1.0f + tanhf(0.7978845608028654f * (x + 0.044715f * x3)));
}

// Packed-A address (float index) for element (m,k) of an [M,K] A operand.
__device__ __forceinline__ size_t paddrA(int m, int k, int K) {
    const int mb = m >> 7, rm = m & 127;
    const int wm = rm >> 5, mt = (rm >> 4) & 1, lr = rm & 7, ah = (rm >> 3) & 1;
    const int kt = k >> 5, kk = (k >> 3) & 3, lc = k & 3, kh = (k >> 2) & 1;
    const int lane = lr * 4 + lc;
    const int reg  = ah + 2 * kh;
    return ((size_t)mb * (K >> 5) + kt) * 4096 +
           ((((kk * 4 + wm) * 2 + mt) * 32 + lane) * 4 + reg);
}
// Packed-B address (float index) for element (n,k) of W[K,N] viewed as [N,K].
__device__ __forceinline__ size_t paddrB(int n, int k, int K) {
    const int nb = n >> 7, rn = n & 127;
    const int wn = (rn >> 6) & 1, nt = (rn >> 3) & 7, n8 = rn & 7;
    const int kt = k >> 5, kk = (k >> 3) & 3, kh = (k >> 2) & 1;
    const int lane = n8 * 4 + (k & 3);
    return ((size_t)nb * (K >> 5) + kt) * 4096 +
           ((((kk * 2 + wn) * 8 + nt) * 32 + lane) * 2 + kh);
}

// ---------------------------------------------------------------------------
// LN body (shared by prep_kernel and ln_kernel)
// ---------------------------------------------------------------------------
__device__ __forceinline__ void ln_body(
    const float* __restrict__ x, const float* __restrict__ g,
    const float* __restrict__ b, float* __restrict__ o, int p, int tid)
{
    const int m0 = (p >> 3) * 16 + (p & 7);
    const int m1 = m0 + 8;
    const int k0 = ((tid >> 2) << 3) + (tid & 3);
    const int k1 = k0 + 512;

    const float* x0 = x + (size_t)m0 * CDIM;
    const float* x1 = x + (size_t)m1 * CDIM;
    const float a00 = x0[k0], a01 = x0[k0 + 4], a02 = x0[k1], a03 = x0[k1 + 4];
    const float a10 = x1[k0], a11 = x1[k0 + 4], a12 = x1[k1], a13 = x1[k1 + 4];

    float s0 = a00 + a01 + a02 + a03;
    float q0 = a00 * a00 + a01 * a01 + a02 * a02 + a03 * a03;
    float s1 = a10 + a11 + a12 + a13;
    float q1 = a10 * a10 + a11 * a11 + a12 * a12 + a13 * a13;

    #pragma unroll
    for (int off = 16; off > 0; off >>= 1) {
        s0 += __shfl_xor_sync(0xffffffffu, s0, off);
        q0 += __shfl_xor_sync(0xffffffffu, q0, off);
        s1 += __shfl_xor_sync(0xffffffffu, s1, off);
        q1 += __shfl_xor_sync(0xffffffffu, q1, off);
    }
    __shared__ float red[4][8];
    const int wid = tid >> 5;
    if ((tid & 31) == 0) {
        red[0][wid] = s0; red[1][wid] = q0; red[2][wid] = s1; red[3][wid] = q1;
    }
    __syncthreads();
    float ts0 = 0.f, tq0 = 0.f, ts1 = 0.f, tq1 = 0.f;
    #pragma unroll
    for (int w = 0; w < 8; w++) {
        ts0 += red[0][w]; tq0 += red[1][w]; ts1 += red[2][w]; tq1 += red[3][w];
    }

    const float mu0 = ts0 * (1.0f / CDIM);
    const float mu1 = ts1 * (1.0f / CDIM);
    const float r0 = rsqrtf(tq0 * (1.0f / CDIM) - mu0 * mu0 + 1e-5f);
    const float r1 = rsqrtf(tq1 * (1.0f / CDIM) - mu1 * mu1 + 1e-5f);

    #pragma unroll
    for (int gi = 0; gi < 2; gi++) {
        const int k = gi ? k1 : k0;
        const float ga = __ldg(&g[k]), gb = __ldg(&g[k + 4]);
        const float ba = __ldg(&b[k]), bb = __ldg(&b[k + 4]);
        const float xa0 = gi ? a02 : a00, xa1 = gi ? a03 : a01;
        const float xb0 = gi ? a12 : a10, xb1 = gi ? a13 : a11;
        *reinterpret_cast<float4*>(&o[paddrA(m0, k, CDIM)]) = make_float4(
            tf32r((xa0 - mu0) * r0 * ga + ba),
            tf32r((xb0 - mu1) * r1 * ga + ba),
            tf32r((xa1 - mu0) * r0 * gb + bb),
            tf32r((xb1 - mu1) * r1 * gb + bb));
    }
}

__device__ __forceinline__ void wprep_body(
    const float* __restrict__ W, float* __restrict__ O,
    int K, int N, int idx)
{
    const int n  = idx % N;
    const int kb = (idx / N) * 8;
    float v[8];
    #pragma unroll
    for (int i = 0; i < 8; i++)
        v[i] = tf32r(__ldg(&W[(size_t)(kb + i) * N + n]));
    float4* p = reinterpret_cast<float4*>(&O[paddrB(n, kb, K)]);
    p[0] = make_float4(v[0], v[4], v[1], v[5]);
    p[1] = make_float4(v[2], v[6], v[3], v[7]);
}

// ---------------------------------------------------------------------------
// prep_kernel: weights pack (blocks 0..6143) + LN1 (blocks 6144..10239)
// ---------------------------------------------------------------------------
__global__ __launch_bounds__(256) void prep_kernel(
    const float* __restrict__ w1, const float* __restrict__ w2,
    const float* __restrict__ w3, const float* __restrict__ w4,
    float* __restrict__ o1, float* __restrict__ o2,
    float* __restrict__ o3, float* __restrict__ o4,
    const float* __restrict__ x, const float* __restrict__ ln1_g,
    const float* __restrict__ ln1_b, float* __restrict__ ln1_o)
{
    const int bid = blockIdx.x;
    const int tid = threadIdx.x;
    if (bid < 1536)
        wprep_body(w1, o1, 1024, 3072, bid * 256 + tid);
    else if (bid < 2048)
        wprep_body(w2, o2, 1024, 1024, (bid - 1536) * 256 + tid);
    else if (bid < 4096)
        wprep_body(w3, o3, 1024, 4096, (bid - 2048) * 256 + tid);
    else if (bid < 6144)
        wprep_body(w4, o4, 4096, 1024, (bid - 4096) * 256 + tid);
    else
        ln_body(x, ln1_g, ln1_b, ln1_o, bid - 6144, tid);
}

__global__ __launch_bounds__(256) void ln_kernel(
    const float* __restrict__ x, const float* __restrict__ g,
    const float* __restrict__ b, float* __restrict__ o)
{
    ln_body(x, g, b, o, blockIdx.x, threadIdx.x);
}

// ---------------------------------------------------------------------------
// tf32 mma.sync GEMM, fragment-packed operands.
// CTA tile 64x128, 128 threads, 4 warps (2m x 2n), warp tile 32x64.
// GSTG=2, bulk loads (A: 4x2KB segments, B: 16KB), 4 CTAs/SM.
// Stage = A 8KB + B 16KB = 24KB. Smem total 1KB + 48KB = 50176 B.
// Pipeline: WAIT(t) -> sync -> ISSUE(t+1) -> compute(t).
// ---------------------------------------------------------------------------
#define GSTG 2
#define STG_FLOATS 6144
#define GEMM_SMEM (1024 + GSTG * STG_FLOATS * 4)

__global__ __launch_bounds__(128, 4) void mma_gemm(
    const float* __restrict__ Apk, const float* __restrict__ Bpk,
    const float* __restrict__ bias, const float* __restrict__ resid,
    float* __restrict__ C, int M, int N, int K, int act, int pack_out,
    int round_out)
{
    extern __shared__ float sm[];
    const uint32_t sb = smem_u32(sm);
    const uint32_t tiles_u = sb + 1024;
    float* tiles_f = sm + 256;

    const int tid  = threadIdx.x;
    const int wid  = tid >> 5;
    const int lane = tid & 31;
    const int wm = wid & 1;              // 32-row group within 64
    const int wn = wid >> 1;             // 64-col half
    const int bm = blockIdx.y << 6;      // 64 rows per CTA
    const int bn = blockIdx.x << 7;
    const int lr = lane >> 2;
    const int lc = lane & 3;

    const int nk = K >> 5;
    const int half = blockIdx.y & 1;     // which 64-row half of the packed 128-row tile
    const char* abase = (const char*)Apk + (size_t)(blockIdx.y >> 1) * nk * 16384;
    const char* bbase = (const char*)Bpk + (size_t)blockIdx.x * nk * 16384;

    if (tid == 0) {
        MBARRIER_INIT(sb,     1);
        MBARRIER_INIT(sb + 8, 1);
        FENCE_PROXY_ASYNC();
    }
    __syncthreads();

    float acc[2][8][4];
    #pragma unroll
    for (int at = 0; at < 2; at++)
        #pragma unroll
        for (int nt = 0; nt < 8; nt++)
            #pragma unroll
            for (int j = 0; j < 4; j++) acc[at][nt][j] = 0.f;

    // stage: A = 4 segments of 2KB (one per kk, our 64-row half), B = 16KB
    #define ISSUEB(t) do { \
        if ((t) < nk && tid == 0) { \
            const uint32_t _m = sb + 8 * ((t) & 1); \
            const uint32_t _d = tiles_u + ((t) & 1) * 24576; \
            const char* _a = abase + (size_t)(t) * 16384 + half * 2048; \
            MBARRIER_EXPECT_TX(_m, 24576u); \
            bulk_g2s(_d,        _a,         2048u, _m); \
            bulk_g2s(_d + 2048, _a + 4096,  2048u, _m); \
            bulk_g2s(_d + 4096, _a + 8192,  2048u, _m); \
            bulk_g2s(_d + 6144, _a + 12288, 2048u, _m); \
            bulk_g2s(_d + 8192, bbase + (size_t)(t) * 16384, 16384u, _m); \
        } \
    } while (0)

    ISSUEB(0);

    for (int t = 0; t < nk; t++) {
        MBARRIER_WAIT_PARITY(sb + 8 * (t & 1), (uint32_t)((t >> 1) & 1));
        __syncthreads();   // all warps retired reads of stage (t-1)&1
        ISSUEB(t + 1);     // overwrites stage (t+1)&1 == (t-1)&1 — safe

        const float* Ab = tiles_f + (t & 1) * STG_FLOATS;
        const float* Bb = Ab + 2048;
        #pragma unroll
        for (int kk = 0; kk < 4; kk++) {
            uint4 a[2];
            #pragma unroll
            for (int at = 0; at < 2; at++)
                a[at] = *reinterpret_cast<const uint4*>(
                    Ab + kk * 512 + (wm * 2 + at) * 128 + lane * 4);
            const float* bq = Bb + (kk * 2 + wn) * 512 + lane * 2;
            #pragma unroll
            for (int nt = 0; nt < 8; nt++) {
                const uint2 bv = *reinterpret_cast<const uint2*>(bq + nt * 64);
                #pragma unroll
                for (int at = 0; at < 2; at++)
                    mma_tf32(acc[at][nt], a[at].x, a[at].y, a[at].z, a[at].w,
                             bv.x, bv.y);
            }
        }
    }

    #pragma unroll
    for (int at = 0; at < 2; at++) {
        const int r0 = bm + wm * 32 + at * 16 + lr;
        const int r1 = r0 + 8;
        #pragma unroll
        for (int nt = 0; nt < 8; nt++) {
            const int col = bn + wn * 64 + nt * 8 + lc * 2;
            const float bb0 = __ldg(&bias[col]);
            const float bb1 = __ldg(&bias[col + 1]);
            float v0 = acc[at][nt][0] + bb0;
            float v1 = acc[at][nt][1] + bb1;
            float v2 = acc[at][nt][2] + bb0;
            float v3 = acc[at][nt][3] + bb1;
            if (act) {
                v0 = gelu_f(v0); v1 = gelu_f(v1);
                v2 = gelu_f(v2); v3 = gelu_f(v3);
            }
            if (pack_out) {
                const float u0 = __shfl_xor_sync(0xffffffffu, v0, 2);
                const float u1 = __shfl_xor_sync(0xffffffffu, v1, 2);
                const float u2 = __shfl_xor_sync(0xffffffffu, v2, 2);
                const float u3 = __shfl_xor_sync(0xffffffffu, v3, 2);
                if (lc < 2) {
                    *reinterpret_cast<float4*>(&C[paddrA(r0, col, N)]) =
                        make_float4(tf32r(v0), tf32r(v2), tf32r(u0), tf32r(u2));
                } else {
                    const int colo = col - 3;
                    *reinterpret_cast<float4*>(&C[paddrA(r0, colo, N)]) =
                        make_float4(tf32r(u1), tf32r(u3), tf32r(v1), tf32r(v3));
                }
            } else {
                const size_t o0 = (size_t)r0 * N + col;
                const size_t o1 = (size_t)r1 * N + col;
                if (resid) {
                    const float2 q0 = *reinterpret_cast<const float2*>(&resid[o0]);
                    const float2 q1 = *reinterpret_cast<const float2*>(&resid[o1]);
                    v0 += q0.x; v1 += q0.y; v2 += q1.x; v3 += q1.y;
                }
                if (round_out) {
                    v0 = tf32r(v0); v1 = tf32r(v1); v2 = tf32r(v2); v3 = tf32r(v3);
                }
                *reinterpret_cast<float2*>(&C[o0]) = make_float2(v0, v1);
                *reinterpret_cast<float2*>(&C[o1]) = make_float2(v2, v3);
            }
        }
    }
}

// ---------------------------------------------------------------------------
// Flash attention on mma.sync tf32, causal — unchanged from R16 (cp.async).
// ---------------------------------------------------------------------------
#define AST_K 68
#define AST_V 72
#define ATT_QOFF 0
#define ATT_KOFF(b) (8704 + (b) * 4352)
#define ATT_VOFF(b) (17408 + (b) * 4608)
#define ATT_SMEM (26624 * 4)

__global__ __launch_bounds__(128, 2) void attn_mma(
    const float* __restrict__ qkv, float* __restrict__ out)
{
    extern __shared__ float sm[];
    const uint32_t sb = smem_u32(sm);
    const int tid = threadIdx.x;
    const int w = tid >> 5, lane = tid & 31;
    const int lr = lane >> 2, lc = lane & 3;
    const int qt = (int)gridDim.x - 1 - (int)blockIdx.x;
    const int bh = blockIdx.y;
    const int b = bh >> 4, h = bh & 15;
    const int q0 = qt * 128;
    const float* basep = qkv + (size_t)b * 2048 * 3072 + (size_t)h * 64;

    #pragma unroll
    for (int i = 0; i < 16; i++) {
        const int idx = tid + i * 128, row = idx >> 4, ch = idx & 15;
        CP_ASYNC16(sb + (uint32_t)(ATT_QOFF + row * AST_K + ch * 4) * 4,
                   basep + (size_t)(q0 + row) * 3072 + ch * 4);
    }
    CP_COMMIT();

    #define ISSUE_KV(kt_, bb) do { \
        const float* _k = basep + (size_t)((kt_) * 64) * 3072 + 1024; \
        _Pragma("unroll") \
        for (int _i = 0; _i < 8; _i++) { \
            const int _idx = tid + _i * 128, _r = _idx >> 4, _c = _idx & 15; \
            CP_ASYNC16(sb + (uint32_t)(ATT_KOFF(bb) + _r * AST_K + _c * 4) * 4, \
                       _k + (size_t)_r * 3072 + _c * 4); \
            CP_ASYNC16(sb + (uint32_t)(ATT_VOFF(bb) + _r * AST_V + _c * 4) * 4, \
                       _k + 1024 + (size_t)_r * 3072 + _c * 4); \
        } \
        CP_COMMIT(); \
    } while (0)

    ISSUE_KV(0, 0);

    CP_WAIT1();
    __syncthreads();

    float qa[2][8][4];
    {
        const float* Qs = sm + ATT_QOFF;
        #pragma unroll
        for (int mt2 = 0; mt2 < 2; mt2++) {
            const int r0 = w * 32 + mt2 * 16 + lr;
            #pragma unroll
            for (int kk = 0; kk < 8; kk++) {
                qa[mt2][kk][0] = 0.125f * Qs[r0 * AST_K + kk * 8 + lc];
                qa[mt2][kk][1] = 0.125f * Qs[(r0 + 8) * AST_K + kk * 8 + lc];
                qa[mt2][kk][2] = 0.125f * Qs[r0 * AST_K + kk * 8 + lc + 4];
                qa[mt2][kk][3] = 0.125f * Qs[(r0 + 8) * AST_K + kk * 8 + lc + 4];
            }
        }
    }
    __syncthreads();

    float* Pw = sm + ATT_QOFF + w * 2048;

    float m[2][2], l[2][2];
    #pragma unroll
    for (int i = 0; i < 2; i++)
        #pragma unroll
        for (int j2 = 0; j2 < 2; j2++) { m[i][j2] = -1e30f; l[i][j2] = 0.f; }

    float o[4][4][4];
    #pragma unroll
    for (int mt = 0; mt < 4; mt++)
        #pragma unroll
        for (int qn = 0; qn < 4; qn++)
            #pragma unroll
            for (int j = 0; j < 4; j++) o[mt][qn][j] = 0.f;

    const int ktmax = 2 * qt + 1;
    for (int kt = 0; kt <= ktmax; kt++) {
        const int buf = kt & 1;
        CP_WAIT0();
        __syncthreads();
        if (kt < ktmax) ISSUE_KV(kt + 1, buf ^ 1);

        if (64 * kt <= q0 + w * 32 + 31) {
            const float* Ks = sm + ATT_KOFF(buf);
            const float* Vs = sm + ATT_VOFF(buf);

            float s[2][8][4];
            #pragma unroll
            for (int mt2 = 0; mt2 < 2; mt2++)
                #pragma unroll
                for (int nt = 0; nt < 8; nt++)
                    #pragma unroll
                    for (int j = 0; j < 4; j++) s[mt2][nt][j] = 0.f;

            #pragma unroll
            for (int kk = 0; kk < 8; kk++) {
                #pragma unroll
                for (int nt = 0; nt < 8; nt++) {
                    const uint32_t b0 = __float_as_uint(Ks[(nt * 8 + lr) * AST_K + kk * 8 + lc]);
                    const uint32_t b1 = __float_as_uint(Ks[(nt * 8 + lr) * AST_K + kk * 8 + lc + 4]);
                    mma_tf32(s[0][nt],
                             __float_as_uint(qa[0][kk][0]), __float_as_uint(qa[0][kk][1]),
                             __float_as_uint(qa[0][kk][2]), __float_as_uint(qa[0][kk][3]),
                             b0, b1);
                    mma_tf32(s[1][nt],
                             __float_as_uint(qa[1][kk][0]), __float_as_uint(qa[1][kk][1]),
                             __float_as_uint(qa[1][kk][2]), __float_as_uint(qa[1][kk][3]),
                             b0, b1);
                }
            }

            #pragma unroll
            for (int mt2 = 0; mt2 < 2; mt2++) {
                const int rbase = q0 + w * 32 + mt2 * 16;
                if (64 * kt + 63 > rbase) {
                    #pragma unroll
                    for (int nt = 0; nt < 8; nt++) {
                        const int c = 64 * kt + nt * 8 + 2 * lc;
                        if (c     > rbase + lr)     s[mt2][nt][0] = -1e30f;
                        if (c + 1 > rbase + lr)     s[mt2][nt][1] = -1e30f;
                        if (c     > rbase + lr + 8) s[mt2][nt][2] = -1e30f;
                        if (c + 1 > rbase + lr + 8) s[mt2][nt][3] = -1e30f;
                    }
                }
            }

            float al[2][2];
            #pragma unroll
            for (int mt2 = 0; mt2 < 2; mt2++) {
                float mx0 = -1e30f, mx1 = -1e30f;
                #pragma unroll
                for (int nt = 0; nt < 8; nt++) {
                    mx0 = fmaxf(mx0, fmaxf(s[mt2][nt][0], s[mt2][nt][1]));
                    mx1 = fmaxf(mx1, fmaxf(s[mt2][nt][2], s[mt2][nt][3]));
                }
                mx0 = fmaxf(mx0, __shfl_xor_sync(0xffffffffu, mx0, 1));
                mx0 = fmaxf(mx0, __shfl_xor_sync(0xffffffffu, mx0, 2));
                mx1 = fmaxf(mx1, __shfl_xor_sync(0xffffffffu, mx1, 1));
                mx1 = fmaxf(mx1, __shfl_xor_sync(0xffffffffu, mx1, 2));

                const float mn0 = fmaxf(m[mt2][0], mx0);
                const float mn1 = fmaxf(m[mt2][1], mx1);
                al[mt2][0] = __expf(m[mt2][0] - mn0);
                al[mt2][1] = __expf(m[mt2][1] - mn1);
                m[mt2][0] = mn0; m[mt2][1] = mn1;

                float sum0 = 0.f, sum1 = 0.f;
                #pragma unroll
                for (int nt = 0; nt < 8; nt++) {
                    s[mt2][nt][0] = __expf(s[mt2][nt][0] - mn0); sum0 += s[mt2][nt][0];
                    s[mt2][nt][1] = __expf(s[mt2][nt][1] - mn0); sum0 += s[mt2][nt][1];
                    s[mt2][nt][2] = __expf(s[mt2][nt][2] - mn1); sum1 += s[mt2][nt][2];
                    s[mt2][nt][3] = __expf(s[mt2][nt][3] - mn1); sum1 += s[mt2][nt][3];
                }
                sum0 += __shfl_xor_sync(0xffffffffu, sum0, 1);
                sum0 += __shfl_xor_sync(0xffffffffu, sum0, 2);
                sum1 += __shfl_xor_sync(0xffffffffu, sum1, 1);
                sum1 += __shfl_xor_sync(0xffffffffu, sum1, 2);
                l[mt2][0] = l[mt2][0] * al[mt2][0] + sum0;
                l[mt2][1] = l[mt2][1] * al[mt2][1] + sum1;
            }

            #pragma unroll
            for (int qn = 0; qn < 4; qn++) {
                const float zA  = __shfl_sync(0xffffffffu, al[qn >> 1][qn & 1], 8 * lc);
                const float zAb = __shfl_sync(0xffffffffu, al[qn >> 1][qn & 1], 8 * lc + 4);
                #pragma unroll
                for (int mt = 0; mt < 4; mt++) {
                    o[mt][qn][0] *= zA;  o[mt][qn][1] *= zAb;
                    o[mt][qn][2] *= zA;  o[mt][qn][3] *= zAb;
                }
            }

            __syncwarp();
            {
                const int c0c = 2 * lc, c1c = 2 * lc + 1;
                const int ln0 = lr * 4 + (c0c & 3), rg0 = (c0c & 4) >> 2;
                const int ln1 = lr * 4 + (c1c & 3), rg1 = (c1c & 4) >> 2;
                #pragma unroll
                for (int mt2 = 0; mt2 < 2; mt2++) {
                    #pragma unroll
                    for (int nt = 0; nt < 8; nt++) {
                        const int q0n = mt2 * 2;
                        Pw[(nt * 4 + q0n + 0) * 64 + ln0 * 2 + rg0] = tf32r(s[mt2][nt][0]);
                        Pw[(nt * 4 + q0n + 0) * 64 + ln1 * 2 + rg1] = tf32r(s[mt2][nt][1]);
                        Pw[(nt * 4 + q0n + 1) * 64 + ln0 * 2 + rg0] = tf32r(s[mt2][nt][2]);
                        Pw[(nt * 4 + q0n + 1) * 64 + ln1 * 2 + rg1] = tf32r(s[mt2][nt][3]);
                    }
                }
            }
            __syncwarp();

            #pragma unroll
            for (int kk2 = 0; kk2 < 8; kk2++) {
                uint2 bp[4];
                #pragma unroll
                for (int qn = 0; qn < 4; qn++)
                    bp[qn] = *reinterpret_cast<const uint2*>(
                        Pw + (kk2 * 4 + qn) * 64 + lane * 2);
                #pragma unroll
                for (int mt = 0; mt < 4; mt++) {
                    const uint32_t a0 = __float_as_uint(Vs[(kk2 * 8 + lc) * AST_V + mt * 16 + lr]);
                    const uint32_t a1 = __float_as_uint(Vs[(kk2 * 8 + lc) * AST_V + mt * 16 + lr + 8]);
                    const uint32_t a2 = __float_as_uint(Vs[(kk2 * 8 + lc + 4) * AST_V + mt * 16 + lr]);
                    const uint32_t a3 = __float_as_uint(Vs[(kk2 * 8 + lc + 4) * AST_V + mt * 16 + lr + 8]);
                    #pragma unroll
                    for (int qn = 0; qn < 4; qn++)
                        mma_tf32(o[mt][qn], a0, a1, a2, a3, bp[qn].x, bp[qn].y);
                }
            }
        }
    }

    float zI[4], zIb[4];
    #pragma unroll
    for (int qn = 0; qn < 4; qn++) {
        const float inv = 1.0f / l[qn >> 1][qn & 1];
        zI[qn]  = __shfl_sync(0xffffffffu, inv, 8 * lc);
        zIb[qn] = __shfl_sync(0xffffffffu, inv, 8 * lc + 4);
    }

    #pragma unroll
    for (int mt = 0; mt < 4; mt++) {
        #pragma unroll
        for (int p = 0; p < 2; p++) {
            float f[2][4];
            #pragma unroll
            for (int h2 = 0; h2 < 2; h2++) {
                const int qn = 2 * p + h2;
                f[h2][0] = o[mt][qn][0] * zI[qn];
                f[h2][1] = o[mt][qn][1] * zIb[qn];
                f[h2][2] = o[mt][qn][2] * zI[qn];
                f[h2][3] = o[mt][qn][3] * zIb[qn];
            }
            float e[2][4];
            #pragma unroll
            for (int h2 = 0; h2 < 2; h2++)
                #pragma unroll
                for (int j = 0; j < 4; j++)
                    e[h2][j] = __shfl_xor_sync(0xffffffffu, f[h2][j], 16);

            const int qr0 = b * 2048 + q0 + w * 32 + p * 16 + 2 * lc;
            if (lr < 4) {
                const int k0 = h * 64 + mt * 16 + lr;
                *reinterpret_cast<float4*>(&out[paddrA(qr0, k0, CDIM)]) =
                    make_float4(tf32r(f[0][0]), tf32r(f[1][0]), tf32r(e[0][0]), tf32r(e[1][0]));
                *reinterpret_cast<float4*>(&out[paddrA(qr0 + 1, k0, CDIM)]) =
                    make_float4(tf32r(f[0][1]), tf32r(f[1][1]), tf32r(e[0][1]), tf32r(e[1][1]));
            } else {
                const int kb = h * 64 + mt * 16 + lr + 4;
                *reinterpret_cast<float4*>(&out[paddrA(qr0, kb, CDIM)]) =
                    make_float4(tf32r(e[0][2]), tf32r(e[1][2]), tf32r(f[0][2]), tf32r(f[1][2]));
                *reinterpret_cast<float4*>(&out[paddrA(qr0 + 1, kb, CDIM)]) =
                    make_float4(tf32r(e[0][3]), tf32r(e[1][3]), tf32r(f[0][3]), tf32r(f[1][3]));
            }
        }
    }
}

// ---------------------------------------------------------------------------
// Launch
// ---------------------------------------------------------------------------
extern "C" void kernel_launch(void* const* d_in, const int* in_sizes, int n_in,
                              void* d_out, int out_size)
{
    const float* x        = (const float*)d_in[0];
    const float* c_attn_w = (const float*)d_in[1];
    const float* c_attn_b = (const float*)d_in[2];
    const float* c_proj_w = (const float*)d_in[3];
    const float* c_proj_b = (const float*)d_in[4];
    const float* fc_w     = (const float*)d_in[5];
    const float* fc_b     = (const float*)d_in[6];
    const float* proj_w   = (const float*)d_in[7];
    const float* proj_b   = (const float*)d_in[8];
    const float* ln1_g    = (const float*)d_in[9];
    const float* ln1_b    = (const float*)d_in[10];
    const float* ln2_g    = (const float*)d_in[11];
    const float* ln2_b    = (const float*)d_in[12];

    float *ln1, *qkv, *attn, *x1, *ln2, *hbuf, *w1p, *w2p, *w3p, *w4p;
    cudaGetSymbolAddress((void**)&ln1,  g_ln1);
    cudaGetSymbolAddress((void**)&qkv,  g_qkv);
    cudaGetSymbolAddress((void**)&attn, g_attn);
    cudaGetSymbolAddress((void**)&x1,   g_x1);
    cudaGetSymbolAddress((void**)&ln2,  g_ln2);
    cudaGetSymbolAddress((void**)&hbuf, g_hbuf);
    cudaGetSymbolAddress((void**)&w1p,  g_w1p);
    cudaGetSymbolAddress((void**)&w2p,  g_w2p);
    cudaGetSymbolAddress((void**)&w3p,  g_w3p);
    cudaGetSymbolAddress((void**)&w4p,  g_w4p);

    cudaFuncSetAttribute(mma_gemm, cudaFuncAttributeMaxDynamicSharedMemorySize, GEMM_SMEM);
    cudaFuncSetAttribute(attn_mma, cudaFuncAttributeMaxDynamicSharedMemorySize, ATT_SMEM);

    float* outp = (float*)d_out;

    // 0. prep: weight packing + LN1 in one launch
    prep_kernel<<<10240, 256>>>(c_attn_w, c_proj_w, fc_w, proj_w,
                                w1p, w2p, w3p, w4p,
                                x, ln1_g, ln1_b, ln1);

    // 2. qkv = ln1 @ c_attn_w + b  (natural, tf32-rounded for attention)
    mma_gemm<<<dim3(24, 128), 128, GEMM_SMEM>>>(
        ln1, w1p, c_attn_b, nullptr, qkv, MROWS, 3072, 1024, 0, 0, 1);
    // 3. attention (q-tile 128, heavy CTAs first) -> packed A
    attn_mma<<<dim3(16, 64), 128, ATT_SMEM>>>(qkv, attn);
    // 4. x1 = attn @ c_proj_w + b + x
    mma_gemm<<<dim3(8, 128), 128, GEMM_SMEM>>>(
        attn, w2p, c_proj_b, x, x1, MROWS, 1024, 1024, 0, 0, 0);
    // 5. ln2 = LN(x1) (packed A)
    ln_kernel<<<4096, 256>>>(x1, ln2_g, ln2_b, ln2);
    // 6. h = gelu(ln2 @ fc_w + b) (packed out)
    mma_gemm<<<dim3(32, 128), 128, GEMM_SMEM>>>(
        ln2, w3p, fc_b, nullptr, hbuf, MROWS, 4096, 1024, 1, 1, 0);
    // 7. out = h @ proj_w + b + x1
    mma_gemm<<<dim3(8, 128), 128, GEMM_SMEM>>>(
        hbuf, w4p, proj_b, x1, outp, MROWS, 1024, 4096, 0, 0, 0);
}